// round 14
// baseline (speedup 1.0000x reference)
#include <cuda_runtime.h>
#include <cuda_bf16.h>
#include <math.h>
#include <cstdint>

#define NTOK 4096
#define CDIM 256
#define QKD  64
#define NB   4

typedef unsigned long long u64;

// ---------------- scratch (device globals) ----------------
__device__ __align__(256) __nv_bfloat16 g_xt  [(size_t)NB * NTOK * CDIM];  // [b][j][c] bf16
__device__ __align__(256) float         g_pet [(size_t)NTOK * QKD];        // PE^T [i][d] fp32
__device__ __align__(256) __nv_bfloat16 g_qb  [(size_t)NB * NTOK * QKD];   // [b][i][d] (pre-scaled)
__device__ __align__(256) __nv_bfloat16 g_kb  [(size_t)NB * NTOK * QKD];   // [b][j][d]
__device__ __align__(256) uint8_t       g_E8  [(size_t)NB * NTOK * NTOK];  // [b][i][j] e4m3 exp(S)
__device__ __align__(256) uint8_t       g_vb8 [(size_t)NB * CDIM * NTOK];  // [b][c][j] e4m3 (V+b)*w*4096
__device__ __align__(256) float         g_cs  [NB * NTOK];                 // column sums (atomic)
__device__ __align__(256) float         g_w   [NB * NTOK];                 // 4096 / colsum
__device__ __align__(256) __nv_bfloat16 g_aob [(size_t)NB * NTOK * CDIM];  // [b][i][c]
__device__ __align__(256) __nv_bfloat16 g_W1b [CDIM * CDIM];
__device__ __align__(256) __nv_bfloat16 g_W2b [CDIM * CDIM];
__device__ __align__(256) __nv_bfloat16 g_WVb [CDIM * CDIM];
__device__ __align__(256) __nv_bfloat16 g_WQKb[2 * QKD * CDIM];

// ---------------- PTX helpers ----------------
__device__ __forceinline__ uint32_t smem_u32(const void* p) {
    uint32_t a;
    asm("{ .reg .u64 t; cvta.to.shared.u64 t, %1; cvt.u32.u64 %0, t; }" : "=r"(a) : "l"(p));
    return a;
}
#define CP_COMMIT()  asm volatile("cp.async.commit_group;" ::: "memory")
template <int N>
__device__ __forceinline__ void cp_wait() {
    asm volatile("cp.async.wait_group %0;" :: "n"(N) : "memory");
}
__device__ __forceinline__ void cp16(uint32_t d, const void* s) {
    asm volatile("cp.async.cg.shared.global [%0], [%1], 16;" :: "r"(d), "l"(s) : "memory");
}
__device__ __forceinline__ void ldsm4(uint32_t r[4], uint32_t a) {
    asm volatile("ldmatrix.sync.aligned.m8n8.x4.shared.b16 {%0,%1,%2,%3}, [%4];"
                 : "=r"(r[0]), "=r"(r[1]), "=r"(r[2]), "=r"(r[3]) : "r"(a));
}
__device__ __forceinline__ void mma_bf16(float c[4], const uint32_t a[4], const uint32_t b[2]) {
    asm volatile("mma.sync.aligned.m16n8k16.row.col.f32.bf16.bf16.f32 "
                 "{%0,%1,%2,%3}, {%4,%5,%6,%7}, {%8,%9}, {%0,%1,%2,%3};"
                 : "+f"(c[0]), "+f"(c[1]), "+f"(c[2]), "+f"(c[3])
                 : "r"(a[0]), "r"(a[1]), "r"(a[2]), "r"(a[3]), "r"(b[0]), "r"(b[1]));
}
__device__ __forceinline__ void mma_fp8(float c[4], const uint32_t a[4], const uint32_t b[2]) {
    asm volatile("mma.sync.aligned.m16n8k32.row.col.f32.e4m3.e4m3.f32 "
                 "{%0,%1,%2,%3}, {%4,%5,%6,%7}, {%8,%9}, {%0,%1,%2,%3};"
                 : "+f"(c[0]), "+f"(c[1]), "+f"(c[2]), "+f"(c[3])
                 : "r"(a[0]), "r"(a[1]), "r"(a[2]), "r"(a[3]), "r"(b[0]), "r"(b[1]));
}
__device__ __forceinline__ uint32_t bf2(float x, float y) {
    __nv_bfloat162 h = __floats2bfloat162_rn(x, y);
    return *(uint32_t*)&h;
}
__device__ __forceinline__ unsigned short fp8x2(float lo, float hi) {
    unsigned short r;
    asm("cvt.rn.satfinite.e4m3x2.f32 %0, %1, %2;" : "=h"(r) : "f"(hi), "f"(lo));
    return r;
}
__device__ __forceinline__ uint32_t ex2_bf16x2(uint32_t a) {
    uint32_t d; asm("ex2.approx.ftz.bf16x2 %0, %1;" : "=r"(d) : "r"(a)); return d;
}
__device__ __forceinline__ float ex2f(float x) {
    float y; asm("ex2.approx.f32 %0, %1;" : "=f"(y) : "f"(x)); return y;
}
__device__ __forceinline__ float lg2f_a(float x) {
    float y; asm("lg2.approx.f32 %0, %1;" : "=f"(y) : "f"(x)); return y;
}
__device__ __forceinline__ float tanh_a(float x) {
    float y; asm("tanh.approx.f32 %0, %1;" : "=f"(y) : "f"(x)); return y;
}
__device__ __forceinline__ float mishf(float v) {
    float t  = ex2f(v * 1.4426950408889634f);
    float sp = lg2f_a(1.0f + t) * 0.6931471805599453f;
    return v * tanh_a(sp);
}
#define QK_SCL 0.18033688011112042f   /* 0.125 * log2(e), folded into Q */
#define AV_SCL 0.000244140625f        /* 1/4096, undoes Vb rescale */

// ================= shared warp-MMA GEMM mainloop =================
// CTA: 256 thr (8 warps, 4 M x 2 N), tile 128(M) x 128(N).
// K-chunk = 64 bytes/row: 32 bf16 or 64 e4m3.
#define ROWB   80
#define SBOFF  (128 * ROWB)
#define STG    (2 * 128 * ROWB)
#define SMEM4  (4 * STG)
#define SMEM2  (2 * STG)

template <int NCH, int NST, bool FP8>
__device__ __forceinline__ void gemm_main(const char* __restrict__ gA, size_t lda,
                                          const char* __restrict__ gB, size_t ldb,
                                          char* smem, float acc[2][8][4])
{
    const int tid  = threadIdx.x;
    const int lane = tid & 31, wid = tid >> 5;
    const int wr = wid & 3, wc = wid >> 2;
    const uint32_t sb = smem_u32(smem);
    const int r0  = tid >> 2;
    const int seg = tid & 3;

    const uint32_t aOff = (uint32_t)((wr * 32 + (lane & 15)) * ROWB + (lane >> 4) * 16);
    const uint32_t bOff = (uint32_t)(SBOFF + (wc * 64 + (lane & 7)) * ROWB + ((lane >> 3) & 3) * 16);

#pragma unroll
    for (int s = 0; s < NST - 1; ++s) {
        if (s < NCH) {
            uint32_t base = sb + (s % NST) * STG;
#pragma unroll
            for (int h = 0; h < 2; ++h) {
                int row = r0 + h * 64;
                cp16(base + row * ROWB + seg * 16, gA + (size_t)row * lda + (size_t)s * 64 + seg * 16);
                cp16(base + SBOFF + row * ROWB + seg * 16, gB + (size_t)row * ldb + (size_t)s * 64 + seg * 16);
            }
        }
        CP_COMMIT();
    }
    for (int c = 0; c < NCH; ++c) {
        cp_wait<NST - 2>();
        __syncthreads();
        const uint32_t st = sb + (c % NST) * STG;
        uint32_t af[2][2][4], bf[8][4];
#pragma unroll
        for (int mt = 0; mt < 2; ++mt)
#pragma unroll
            for (int ks = 0; ks < 2; ++ks)
                ldsm4(af[mt][ks], st + aOff + mt * (16 * ROWB) + ks * 32);
#pragma unroll
        for (int nt = 0; nt < 8; ++nt)
            ldsm4(bf[nt], st + bOff + nt * (8 * ROWB));
#pragma unroll
        for (int ks = 0; ks < 2; ++ks)
#pragma unroll
            for (int mt = 0; mt < 2; ++mt)
#pragma unroll
                for (int nt = 0; nt < 8; ++nt) {
                    if (FP8) mma_fp8(acc[mt][nt], af[mt][ks], &bf[nt][ks * 2]);
                    else     mma_bf16(acc[mt][nt], af[mt][ks], &bf[nt][ks * 2]);
                }
        __syncthreads();
        if (c + NST - 1 < NCH) {
            uint32_t base = sb + ((c + NST - 1) % NST) * STG;
#pragma unroll
            for (int h = 0; h < 2; ++h) {
                int row = r0 + h * 64;
                cp16(base + row * ROWB + seg * 16, gA + (size_t)row * lda + (size_t)(c + NST - 1) * 64 + seg * 16);
                cp16(base + SBOFF + row * ROWB + seg * 16, gB + (size_t)row * ldb + (size_t)(c + NST - 1) * 64 + seg * 16);
            }
        }
        CP_COMMIT();
    }
}

// ---- phase-2 mainloop for fused MLP: A streamed via A-only ring, B from persistent smem H ----
// K = 256 (o). A-ring stage = 64 B/row = 32 k per chunk -> 8 chunks. H offset per chunk = 64 B.
#define HROWB 528                       /* bytes per H row: 256 bf16 data (512B) + 16B pad */
#define ASTG  (128 * ROWB)              /* A-only stage = 10240 B */
__device__ __forceinline__ void gemm_w2(const char* __restrict__ gA,
                                        uint32_t hsb, char* ring, float acc[2][8][4])
{
    const int tid  = threadIdx.x;
    const int lane = tid & 31, wid = tid >> 5;
    const int wr = wid & 3, wc = wid >> 2;
    const uint32_t sb = smem_u32(ring);
    const int row = tid >> 1, sg = (tid & 1) * 2;

    const uint32_t aOff  = (uint32_t)((wr * 32 + (lane & 15)) * ROWB + (lane >> 4) * 16);
    const uint32_t bOffH = (uint32_t)((wc * 64 + (lane & 7)) * HROWB + ((lane >> 3) & 3) * 16);

#pragma unroll
    for (int s = 0; s < 3; ++s) {
        uint32_t base = sb + s * ASTG;
        cp16(base + row * ROWB + sg * 16,       gA + (size_t)row * 512 + (size_t)s * 64 + sg * 16);
        cp16(base + row * ROWB + (sg + 1) * 16, gA + (size_t)row * 512 + (size_t)s * 64 + (sg + 1) * 16);
        CP_COMMIT();
    }
    for (int c = 0; c < 8; ++c) {
        cp_wait<2>();
        __syncthreads();
        const uint32_t st = sb + (c & 3) * ASTG;
        uint32_t af[2][2][4], bf[8][4];
#pragma unroll
        for (int mt = 0; mt < 2; ++mt)
#pragma unroll
            for (int ks = 0; ks < 2; ++ks)
                ldsm4(af[mt][ks], st + aOff + mt * (16 * ROWB) + ks * 32);
#pragma unroll
        for (int nt = 0; nt < 8; ++nt)
            ldsm4(bf[nt], hsb + bOffH + nt * (8 * HROWB) + c * 64);
#pragma unroll
        for (int ks = 0; ks < 2; ++ks)
#pragma unroll
            for (int mt = 0; mt < 2; ++mt)
#pragma unroll
                for (int nt = 0; nt < 8; ++nt)
                    mma_bf16(acc[mt][nt], af[mt][ks], &bf[nt][ks * 2]);
        __syncthreads();
        if (c + 3 < 8) {
            uint32_t base = sb + ((c + 3) & 3) * ASTG;
            cp16(base + row * ROWB + sg * 16,       gA + (size_t)row * 512 + (size_t)(c + 3) * 64 + sg * 16);
            cp16(base + row * ROWB + (sg + 1) * 16, gA + (size_t)row * 512 + (size_t)(c + 3) * 64 + (sg + 1) * 16);
        }
        CP_COMMIT();
    }
}

#define ACC_DECL  float acc[2][8][4]; \
    _Pragma("unroll") for (int _m = 0; _m < 2; ++_m) \
    _Pragma("unroll") for (int _n = 0; _n < 8; ++_n) \
    _Pragma("unroll") for (int _q = 0; _q < 4; ++_q) acc[_m][_n][_q] = 0.0f;

#define EPI_COORDS \
    const int lane = threadIdx.x & 31, wid = threadIdx.x >> 5; \
    const int wr = wid & 3, wc = wid >> 2; \
    const int rowL = wr * 32 + (lane >> 2); \
    const int colL = wc * 64 + (lane & 3) * 2; \
    (void)wr; (void)wc;

// ---------------- K0: prep — weight conversions + zero colsum ----------------
__device__ __forceinline__ void conv4(const float* s, __nv_bfloat16* d, int i) {
    float4 v = *(const float4*)(s + i);
    *(uint32_t*)(d + i)     = bf2(v.x, v.y);
    *(uint32_t*)(d + i + 2) = bf2(v.z, v.w);
}
__global__ __launch_bounds__(256) void k_prep(
    const float* __restrict__ W1, const float* __restrict__ W2, const float* __restrict__ WV,
    const float* __restrict__ WQ, const float* __restrict__ WK)
{
    int blk = blockIdx.x, t = threadIdx.x;
    if (blk < 16) {
        int base = blk * 4096;
#pragma unroll
        for (int p = 0; p < 4; ++p) conv4(W1, g_W1b, base + p * 1024 + t * 4);
    } else if (blk < 32) {
        int base = (blk - 16) * 4096;
#pragma unroll
        for (int p = 0; p < 4; ++p) conv4(W2, g_W2b, base + p * 1024 + t * 4);
    } else if (blk < 48) {
        int base = (blk - 32) * 4096;
#pragma unroll
        for (int p = 0; p < 4; ++p) conv4(WV, g_WVb, base + p * 1024 + t * 4);
    } else if (blk < 56) {
        int base = (blk - 48) * 4096;
#pragma unroll
        for (int p = 0; p < 4; ++p) {
            int i = base + p * 1024 + t * 4;
            const float* s = (i < QKD * CDIM) ? (WQ + i) : (WK + i - QKD * CDIM);
            float4 v = *(const float4*)s;
            *(uint32_t*)(g_WQKb + i)     = bf2(v.x, v.y);
            *(uint32_t*)(g_WQKb + i + 2) = bf2(v.z, v.w);
        }
    } else {
        int base = (blk - 56) * 4096;
#pragma unroll
        for (int p = 0; p < 4; ++p)
            *(float4*)(g_cs + base + p * 1024 + t * 4) = make_float4(0.f, 0.f, 0.f, 0.f);
    }
}

// ---------------- K0b: x [b][c][j] fp32 -> x_t [b][j][c] bf16 ----------------
__global__ __launch_bounds__(256) void k_xt(const float* __restrict__ x)
{
    __shared__ float ts[32][129];
    const int jt = blockIdx.x * 128, ct = blockIdx.y * 32, b = blockIdx.z;
    const int tid = threadIdx.x;
#pragma unroll
    for (int p = 0; p < 4; ++p) {
        int c = (tid >> 5) + p * 8;
        int j = (tid & 31) * 4;
        float4 v = *(const float4*)(x + ((size_t)b * CDIM + ct + c) * NTOK + jt + j);
        ts[c][j] = v.x; ts[c][j+1] = v.y; ts[c][j+2] = v.z; ts[c][j+3] = v.w;
    }
    __syncthreads();
#pragma unroll
    for (int p = 0; p < 8; ++p) {
        int idx = tid + p * 256;
        int j = idx >> 4, cp = idx & 15;
        *(uint32_t*)(g_xt + ((size_t)b * NTOK + jt + j) * CDIM + ct + cp * 2)
            = bf2(ts[cp * 2][j], ts[cp * 2 + 1][j]);
    }
}

// ---------------- K0c: PE [d][i] -> PEt [i][d] fp32 ----------------
__global__ __launch_bounds__(256) void k_pet(const float* __restrict__ PE)
{
    __shared__ float ts[32][33];
    const int it = blockIdx.x * 32, dt = blockIdx.y * 32;
    const int r = threadIdx.x >> 5, c = threadIdx.x & 31;
#pragma unroll
    for (int p = 0; p < 4; ++p)
        ts[r + p * 8][c] = PE[(size_t)(dt + r + p * 8) * NTOK + it + c];
    __syncthreads();
#pragma unroll
    for (int p = 0; p < 4; ++p)
        g_pet[(size_t)(it + r + p * 8) * QKD + dt + c] = ts[c][r + p * 8];
}

// ---------------- K1: QK projection; Q pre-scaled by QK_SCL ----------------
__global__ __launch_bounds__(256, 2) void k_projqk_w(
    const float* __restrict__ bQ, const float* __restrict__ bK)
{
    extern __shared__ char smem[];
    const int i0 = blockIdx.x * 128, b = blockIdx.y;
    ACC_DECL;
    gemm_main<8, 4, false>((const char*)(g_xt + ((size_t)b * NTOK + i0) * CDIM), 512,
                           (const char*)g_WQKb, 512, smem, acc);
    EPI_COORDS;
    const bool isQ = (wc == 0);
    const float scl = isQ ? QK_SCL : 1.0f;
    __nv_bfloat16* dst = (isQ ? g_qb : g_kb) + (size_t)b * NTOK * QKD;
#pragma unroll
    for (int nt = 0; nt < 8; ++nt) {
        int d = (lane & 3) * 2 + nt * 8;
        float b0 = isQ ? bQ[d]     : bK[d];
        float b1 = isQ ? bQ[d + 1] : bK[d + 1];
#pragma unroll
        for (int mt = 0; mt < 2; ++mt)
#pragma unroll
            for (int h = 0; h < 2; ++h) {
                int row = i0 + rowL + mt * 16 + h * 8;
                float2 pe = *(const float2*)(g_pet + (size_t)row * QKD + d);
                *(uint32_t*)(dst + (size_t)row * QKD + d)
                    = bf2((acc[mt][nt][h*2] + b0 + pe.x) * scl,
                          (acc[mt][nt][h*2+1] + b1 + pe.y) * scl);
            }
    }
}

// ---------------- K2: QK^T mma + exp -> e4m3 E (smem-staged coalesced) + colsum ----------------
// grid (32 j, 32 i, 4 b). Q pre-scaled, so E = 2^(acc).
#define EST8  144   /* staging row stride in bytes: 16B-aligned; rows 4 banks apart */
__global__ __launch_bounds__(256, 2) void k_qkt_w()
{
    extern __shared__ char smem[];
    const int j0 = blockIdx.x * 128, i0 = blockIdx.y * 128, b = blockIdx.z;
    ACC_DECL;
    gemm_main<2, 2, false>((const char*)(g_qb + ((size_t)b * NTOK + i0) * QKD), 128,
                           (const char*)(g_kb + ((size_t)b * NTOK + j0) * QKD), 128,
                           smem, acc);
    EPI_COORDS;
    uint8_t* est = (uint8_t*)smem;     // 128 x 144B staging (18.4 KB)
    float cs[8][2];
#pragma unroll
    for (int nt = 0; nt < 8; ++nt) { cs[nt][0] = 0.f; cs[nt][1] = 0.f; }
#pragma unroll
    for (int mt = 0; mt < 2; ++mt)
#pragma unroll
        for (int nt = 0; nt < 8; ++nt) {
            int col = colL + nt * 8;                 // local col 0..127
#pragma unroll
            for (int h = 0; h < 2; ++h) {
                int row = rowL + mt * 16 + h * 8;    // local row 0..127
                uint32_t ee = ex2_bf16x2(bf2(acc[mt][nt][h*2], acc[mt][nt][h*2+1]));
                float e0 = __int_as_float(ee << 16);
                float e1 = __int_as_float(ee & 0xFFFF0000u);
                *(unsigned short*)(est + row * EST8 + col) = fp8x2(e0, e1);
                cs[nt][0] += e0;
                cs[nt][1] += e1;
            }
        }
    __syncthreads();
    {
        const int tid = threadIdx.x;
        uint8_t* ep = g_E8 + ((size_t)b * NTOK + i0) * NTOK + j0;
#pragma unroll
        for (int p = 0; p < 4; ++p) {
            int idx = tid + p * 256;
            int row = idx >> 3, seg = idx & 7;
            uint4 v = *(const uint4*)(est + row * EST8 + seg * 16);
            *(uint4*)(ep + (size_t)row * NTOK + seg * 16) = v;
        }
    }
#pragma unroll
    for (int nt = 0; nt < 8; ++nt)
#pragma unroll
        for (int p = 0; p < 2; ++p) {
            float v = cs[nt][p];
            v += __shfl_xor_sync(0xFFFFFFFFu, v, 4);
            v += __shfl_xor_sync(0xFFFFFFFFu, v, 8);
            v += __shfl_xor_sync(0xFFFFFFFFu, v, 16);
            cs[nt][p] = v;
        }
    float* sred = (float*)smem;
    __syncthreads();
    if (threadIdx.x < 128) sred[threadIdx.x] = 0.0f;
    __syncthreads();
    if ((lane >> 2) == 0) {
#pragma unroll
        for (int nt = 0; nt < 8; ++nt) {
            int cc = wc * 64 + (lane & 3) * 2 + nt * 8;
            atomicAdd(&sred[cc],     cs[nt][0]);
            atomicAdd(&sred[cc + 1], cs[nt][1]);
        }
    }
    __syncthreads();
    if (threadIdx.x < 128)
        atomicAdd(&g_cs[(size_t)b * NTOK + j0 + threadIdx.x], sred[threadIdx.x]);
}

// ---------------- K2b: w = 4096/colsum ----------------
__global__ __launch_bounds__(256) void k_wcalc()
{
    int idx = blockIdx.x * 256 + threadIdx.x;
    g_w[idx] = 4096.0f / g_cs[idx];
}

// ---------------- K3: V projection (epilogue *w[j]+bias -> e4m3 g_vb8) ----------------
__global__ __launch_bounds__(256, 2) void k_projv_w(const float* __restrict__ bV)
{
    extern __shared__ char smem[];
    const int j0 = blockIdx.x * 128, m0 = blockIdx.y * 128, b = blockIdx.z;
    ACC_DECL;
    gemm_main<8, 4, false>((const char*)(g_WVb + (size_t)m0 * CDIM), 512,
                           (const char*)(g_xt + ((size_t)b * NTOK + j0) * CDIM), 512,
                           smem, acc);
    EPI_COORDS;
#pragma unroll
    for (int mt = 0; mt < 2; ++mt)
#pragma unroll
        for (int h = 0; h < 2; ++h) {
            int row = m0 + rowL + mt * 16 + h * 8;
            float bb = bV[row];
#pragma unroll
            for (int nt = 0; nt < 8; ++nt) {
                int col = j0 + colL + nt * 8;
                float2 w2 = *(const float2*)(g_w + (size_t)b * NTOK + col);
                *(unsigned short*)(g_vb8 + ((size_t)b * CDIM + row) * NTOK + col)
                    = fp8x2((acc[mt][nt][h*2] + bb) * w2.x, (acc[mt][nt][h*2+1] + bb) * w2.y);
            }
        }
}

// ---------------- K4: AO = E @ Vb (fp8 mma, K=4096) -> bf16 ao[i][c] ----------------
__global__ __launch_bounds__(256) void k_av_w()
{
    extern __shared__ char smem[];
    const int n0 = blockIdx.x * 128, i0 = blockIdx.y * 128, b = blockIdx.z;
    ACC_DECL;
    gemm_main<64, 4, true>((const char*)(g_E8  + ((size_t)b * NTOK + i0) * NTOK), 4096,
                           (const char*)(g_vb8 + ((size_t)b * CDIM + n0) * NTOK), 4096,
                           smem, acc);
    EPI_COORDS;
#pragma unroll
    for (int mt = 0; mt < 2; ++mt)
#pragma unroll
        for (int nt = 0; nt < 8; ++nt) {
            int col = n0 + colL + nt * 8;
#pragma unroll
            for (int h = 0; h < 2; ++h) {
                int row = i0 + rowL + mt * 16 + h * 8;
                *(uint32_t*)(g_aob + ((size_t)b * NTOK + row) * CDIM + col)
                    = bf2(acc[mt][nt][h*2] * AV_SCL, acc[mt][nt][h*2+1] * AV_SCL);
            }
        }
}

// ---------------- K5: fused MLP: H = mish(AO@W1^T+b1) in smem; OUT = W2@H^T + b2 + x ----------------
// grid (32 iblk, 4 b), 256 thr. smem: ring (81920) + H (128 x 528B = 67584) = 149504 B
#define MLP_SMEM (SMEM4 + 128 * HROWB)
__global__ __launch_bounds__(256) void k_mlp_f(
    const float* __restrict__ b1, const float* __restrict__ b2,
    const float* __restrict__ x, float* __restrict__ out)
{
    extern __shared__ char smem[];
    char* ring = smem;
    __nv_bfloat16* Hs = (__nv_bfloat16*)(smem + SMEM4);
    const uint32_t hsb = smem_u32(Hs);
    const int i0 = blockIdx.x * 128, b = blockIdx.y;
    EPI_COORDS;

    // ---- phase 1: H tile (128 i x 256 o) -> smem ----
#pragma unroll 1
    for (int ob = 0; ob < 2; ++ob) {
        ACC_DECL;
        gemm_main<8, 4, false>((const char*)(g_aob + ((size_t)b * NTOK + i0) * CDIM), 512,
                               (const char*)(g_W1b + (size_t)ob * 128 * CDIM), 512, ring, acc);
#pragma unroll
        for (int nt = 0; nt < 8; ++nt) {
            int col = ob * 128 + colL + nt * 8;
            float bb0 = b1[col], bb1 = b1[col + 1];
#pragma unroll
            for (int mt = 0; mt < 2; ++mt)
#pragma unroll
                for (int h = 0; h < 2; ++h) {
                    int row = rowL + mt * 16 + h * 8;      // local i row
                    *(uint32_t*)((char*)Hs + row * HROWB + col * 2)
                        = bf2(mishf(acc[mt][nt][h*2] + bb0), mishf(acc[mt][nt][h*2+1] + bb1));
                }
        }
        __syncthreads();   // H writes visible; ring reusable
    }

    // ---- phase 2: OUT (256 c x 128 i) from W2 (streamed) x H (smem) ----
#pragma unroll 1
    for (int cb = 0; cb < 2; ++cb) {
        ACC_DECL;
        gemm_w2((const char*)(g_W2b + (size_t)cb * 128 * CDIM), hsb, ring, acc);
#pragma unroll
        for (int mt = 0; mt < 2; ++mt)
#pragma unroll
            for (int h = 0; h < 2; ++h) {
                int row = cb * 128 + rowL + mt * 16 + h * 8;   // channel c
                float bb = b2[row];
                size_t base = ((size_t)b * CDIM + row) * NTOK;
#pragma unroll
                for (int nt = 0; nt < 8; ++nt) {
                    int col = i0 + colL + nt * 8;
                    float2 xv = *(const float2*)(x + base + col);
                    *(float2*)(out + base + col)
                        = make_float2(acc[mt][nt][h*2]   + bb + xv.x,
                                      acc[mt][nt][h*2+1] + bb + xv.y);
                }
            }
        __syncthreads();   // ring reusable for next cb
    }
}

// ---------------- launch ----------------
extern "C" void kernel_launch(void* const* d_in, const int* in_sizes, int n_in,
                              void* d_out, int out_size)
{
    (void)in_sizes; (void)n_in; (void)out_size;
    const float* x  = (const float*)d_in[0];
    const float* WQ = (const float*)d_in[1];
    const float* bQ = (const float*)d_in[2];
    const float* WK = (const float*)d_in[3];
    const float* bK = (const float*)d_in[4];
    const float* WV = (const float*)d_in[5];
    const float* bV = (const float*)d_in[6];
    const float* PE = (const float*)d_in[7];
    const float* W1 = (const float*)d_in[8];
    const float* b1 = (const float*)d_in[9];
    const float* W2 = (const float*)d_in[10];
    const float* b2 = (const float*)d_in[11];
    float* out = (float*)d_out;

    cudaFuncSetAttribute(k_projqk_w, cudaFuncAttributeMaxDynamicSharedMemorySize, SMEM4);
    cudaFuncSetAttribute(k_qkt_w,    cudaFuncAttributeMaxDynamicSharedMemorySize, SMEM2);
    cudaFuncSetAttribute(k_projv_w,  cudaFuncAttributeMaxDynamicSharedMemorySize, SMEM4);
    cudaFuncSetAttribute(k_av_w,     cudaFuncAttributeMaxDynamicSharedMemorySize, SMEM4);
    cudaFuncSetAttribute(k_mlp_f,    cudaFuncAttributeMaxDynamicSharedMemorySize, MLP_SMEM);

    k_prep    <<<dim3(60),          256>>>(W1, W2, WV, WQ, WK);
    k_xt      <<<dim3(32, 8, NB),   256>>>(x);
    k_pet     <<<dim3(128, 2),      256>>>(PE);
    k_projqk_w<<<dim3(32, NB),      256, SMEM4>>>(bQ, bK);
    k_qkt_w   <<<dim3(32, 32, NB),  256, SMEM2>>>();
    k_wcalc   <<<dim3(64),          256>>>();
    k_projv_w <<<dim3(32, 2, NB),   256, SMEM4>>>(bV);
    k_av_w    <<<dim3(2, 32, NB),   256, SMEM4>>>();
    k_mlp_f   <<<dim3(32, NB),      256, MLP_SMEM>>>(b1, b2, x, out);
}

// round 15
// speedup vs baseline: 1.0136x; 1.0136x over previous
#include <cuda_runtime.h>
#include <cuda_bf16.h>
#include <math.h>
#include <cstdint>

#define NTOK 4096
#define CDIM 256
#define QKD  64
#define NB   4

typedef unsigned long long u64;

// ---------------- scratch (device globals) ----------------
__device__ __align__(256) __nv_bfloat16 g_xt  [(size_t)NB * NTOK * CDIM];  // [b][j][c] bf16
__device__ __align__(256) float         g_pet [(size_t)NTOK * QKD];        // PE^T [i][d] fp32
__device__ __align__(256) __nv_bfloat16 g_qb  [(size_t)NB * NTOK * QKD];   // [b][i][d] (pre-scaled)
__device__ __align__(256) __nv_bfloat16 g_kb  [(size_t)NB * NTOK * QKD];   // [b][j][d]
__device__ __align__(256) uint8_t       g_E8  [(size_t)NB * NTOK * NTOK];  // [b][i][j] e4m3 exp(S)
__device__ __align__(256) uint8_t       g_vb8 [(size_t)NB * CDIM * NTOK];  // [b][c][j] e4m3 (V+b)*w*4096
__device__ __align__(256) float         g_cs  [NB * NTOK];                 // column sums (atomic)
__device__ __align__(256) float         g_w   [NB * NTOK];                 // 4096 / colsum
__device__ __align__(256) __nv_bfloat16 g_aob [(size_t)NB * NTOK * CDIM];  // [b][i][c]
__device__ __align__(256) __nv_bfloat16 g_W1b [CDIM * CDIM];
__device__ __align__(256) __nv_bfloat16 g_W2b [CDIM * CDIM];
__device__ __align__(256) __nv_bfloat16 g_WVb [CDIM * CDIM];
__device__ __align__(256) __nv_bfloat16 g_WQKb[2 * QKD * CDIM];

// ---------------- PTX helpers ----------------
__device__ __forceinline__ uint32_t smem_u32(const void* p) {
    uint32_t a;
    asm("{ .reg .u64 t; cvta.to.shared.u64 t, %1; cvt.u32.u64 %0, t; }" : "=r"(a) : "l"(p));
    return a;
}
#define CP_COMMIT()  asm volatile("cp.async.commit_group;" ::: "memory")
template <int N>
__device__ __forceinline__ void cp_wait() {
    asm volatile("cp.async.wait_group %0;" :: "n"(N) : "memory");
}
__device__ __forceinline__ void cp16(uint32_t d, const void* s) {
    asm volatile("cp.async.cg.shared.global [%0], [%1], 16;" :: "r"(d), "l"(s) : "memory");
}
__device__ __forceinline__ void ldsm4(uint32_t r[4], uint32_t a) {
    asm volatile("ldmatrix.sync.aligned.m8n8.x4.shared.b16 {%0,%1,%2,%3}, [%4];"
                 : "=r"(r[0]), "=r"(r[1]), "=r"(r[2]), "=r"(r[3]) : "r"(a));
}
__device__ __forceinline__ void mma_bf16(float c[4], const uint32_t a[4], const uint32_t b[2]) {
    asm volatile("mma.sync.aligned.m16n8k16.row.col.f32.bf16.bf16.f32 "
                 "{%0,%1,%2,%3}, {%4,%5,%6,%7}, {%8,%9}, {%0,%1,%2,%3};"
                 : "+f"(c[0]), "+f"(c[1]), "+f"(c[2]), "+f"(c[3])
                 : "r"(a[0]), "r"(a[1]), "r"(a[2]), "r"(a[3]), "r"(b[0]), "r"(b[1]));
}
__device__ __forceinline__ void mma_fp8(float c[4], const uint32_t a[4], const uint32_t b[2]) {
    asm volatile("mma.sync.aligned.m16n8k32.row.col.f32.e4m3.e4m3.f32 "
                 "{%0,%1,%2,%3}, {%4,%5,%6,%7}, {%8,%9}, {%0,%1,%2,%3};"
                 : "+f"(c[0]), "+f"(c[1]), "+f"(c[2]), "+f"(c[3])
                 : "r"(a[0]), "r"(a[1]), "r"(a[2]), "r"(a[3]), "r"(b[0]), "r"(b[1]));
}
__device__ __forceinline__ uint32_t bf2(float x, float y) {
    __nv_bfloat162 h = __floats2bfloat162_rn(x, y);
    return *(uint32_t*)&h;
}
__device__ __forceinline__ unsigned short fp8x2(float lo, float hi) {
    unsigned short r;
    asm("cvt.rn.satfinite.e4m3x2.f32 %0, %1, %2;" : "=h"(r) : "f"(hi), "f"(lo));
    return r;
}
__device__ __forceinline__ uint32_t ex2_bf16x2(uint32_t a) {
    uint32_t d; asm("ex2.approx.ftz.bf16x2 %0, %1;" : "=r"(d) : "r"(a)); return d;
}
__device__ __forceinline__ float ex2f(float x) {
    float y; asm("ex2.approx.f32 %0, %1;" : "=f"(y) : "f"(x)); return y;
}
__device__ __forceinline__ float lg2f_a(float x) {
    float y; asm("lg2.approx.f32 %0, %1;" : "=f"(y) : "f"(x)); return y;
}
__device__ __forceinline__ float tanh_a(float x) {
    float y; asm("tanh.approx.f32 %0, %1;" : "=f"(y) : "f"(x)); return y;
}
__device__ __forceinline__ float mishf(float v) {
    float t  = ex2f(v * 1.4426950408889634f);
    float sp = lg2f_a(1.0f + t) * 0.6931471805599453f;
    return v * tanh_a(sp);
}
#define QK_SCL 0.18033688011112042f   /* 0.125 * log2(e), folded into Q */
#define AV_SCL 0.000244140625f        /* 1/4096, undoes Vb rescale */

// ================= shared warp-MMA GEMM mainloop =================
// CTA: 256 thr (8 warps, 4 M x 2 N), tile 128(M) x 128(N).
// K-chunk = 64 bytes/row: 32 bf16 or 64 e4m3.
#define ROWB   80
#define SBOFF  (128 * ROWB)
#define STG    (2 * 128 * ROWB)
#define SMEM4  (4 * STG)
#define SMEM2  (2 * STG)

template <int NCH, int NST, bool FP8>
__device__ __forceinline__ void gemm_main(const char* __restrict__ gA, size_t lda,
                                          const char* __restrict__ gB, size_t ldb,
                                          char* smem, float acc[2][8][4])
{
    const int tid  = threadIdx.x;
    const int lane = tid & 31, wid = tid >> 5;
    const int wr = wid & 3, wc = wid >> 2;
    const uint32_t sb = smem_u32(smem);
    const int r0  = tid >> 2;
    const int seg = tid & 3;

    const uint32_t aOff = (uint32_t)((wr * 32 + (lane & 15)) * ROWB + (lane >> 4) * 16);
    const uint32_t bOff = (uint32_t)(SBOFF + (wc * 64 + (lane & 7)) * ROWB + ((lane >> 3) & 3) * 16);

#pragma unroll
    for (int s = 0; s < NST - 1; ++s) {
        if (s < NCH) {
            uint32_t base = sb + (s % NST) * STG;
#pragma unroll
            for (int h = 0; h < 2; ++h) {
                int row = r0 + h * 64;
                cp16(base + row * ROWB + seg * 16, gA + (size_t)row * lda + (size_t)s * 64 + seg * 16);
                cp16(base + SBOFF + row * ROWB + seg * 16, gB + (size_t)row * ldb + (size_t)s * 64 + seg * 16);
            }
        }
        CP_COMMIT();
    }
    for (int c = 0; c < NCH; ++c) {
        cp_wait<NST - 2>();
        __syncthreads();
        const uint32_t st = sb + (c % NST) * STG;
        uint32_t af[2][2][4], bf[8][4];
#pragma unroll
        for (int mt = 0; mt < 2; ++mt)
#pragma unroll
            for (int ks = 0; ks < 2; ++ks)
                ldsm4(af[mt][ks], st + aOff + mt * (16 * ROWB) + ks * 32);
#pragma unroll
        for (int nt = 0; nt < 8; ++nt)
            ldsm4(bf[nt], st + bOff + nt * (8 * ROWB));
#pragma unroll
        for (int ks = 0; ks < 2; ++ks)
#pragma unroll
            for (int mt = 0; mt < 2; ++mt)
#pragma unroll
                for (int nt = 0; nt < 8; ++nt) {
                    if (FP8) mma_fp8(acc[mt][nt], af[mt][ks], &bf[nt][ks * 2]);
                    else     mma_bf16(acc[mt][nt], af[mt][ks], &bf[nt][ks * 2]);
                }
        __syncthreads();
        if (c + NST - 1 < NCH) {
            uint32_t base = sb + ((c + NST - 1) % NST) * STG;
#pragma unroll
            for (int h = 0; h < 2; ++h) {
                int row = r0 + h * 64;
                cp16(base + row * ROWB + seg * 16, gA + (size_t)row * lda + (size_t)(c + NST - 1) * 64 + seg * 16);
                cp16(base + SBOFF + row * ROWB + seg * 16, gB + (size_t)row * ldb + (size_t)(c + NST - 1) * 64 + seg * 16);
            }
        }
        CP_COMMIT();
    }
}

// ---- phase-2 mainloop for fused MLP: A streamed via A-only ring, B from persistent smem H ----
// K = 256 (o). A-ring stage = 64 B/row = 32 k per chunk -> 8 chunks. H offset per chunk = 64 B.
#define HROWB 528                       /* bytes per H row: 256 bf16 data (512B) + 16B pad */
#define ASTG  (128 * ROWB)              /* A-only stage = 10240 B */
__device__ __forceinline__ void gemm_w2(const char* __restrict__ gA,
                                        uint32_t hsb, char* ring, float acc[2][8][4])
{
    const int tid  = threadIdx.x;
    const int lane = tid & 31, wid = tid >> 5;
    const int wr = wid & 3, wc = wid >> 2;
    const uint32_t sb = smem_u32(ring);
    const int row = tid >> 1, sg = (tid & 1) * 2;

    const uint32_t aOff  = (uint32_t)((wr * 32 + (lane & 15)) * ROWB + (lane >> 4) * 16);
    const uint32_t bOffH = (uint32_t)((wc * 64 + (lane & 7)) * HROWB + ((lane >> 3) & 3) * 16);

#pragma unroll
    for (int s = 0; s < 3; ++s) {
        uint32_t base = sb + s * ASTG;
        cp16(base + row * ROWB + sg * 16,       gA + (size_t)row * 512 + (size_t)s * 64 + sg * 16);
        cp16(base + row * ROWB + (sg + 1) * 16, gA + (size_t)row * 512 + (size_t)s * 64 + (sg + 1) * 16);
        CP_COMMIT();
    }
    for (int c = 0; c < 8; ++c) {
        cp_wait<2>();
        __syncthreads();
        const uint32_t st = sb + (c & 3) * ASTG;
        uint32_t af[2][2][4], bf[8][4];
#pragma unroll
        for (int mt = 0; mt < 2; ++mt)
#pragma unroll
            for (int ks = 0; ks < 2; ++ks)
                ldsm4(af[mt][ks], st + aOff + mt * (16 * ROWB) + ks * 32);
#pragma unroll
        for (int nt = 0; nt < 8; ++nt)
            ldsm4(bf[nt], hsb + bOffH + nt * (8 * HROWB) + c * 64);
#pragma unroll
        for (int ks = 0; ks < 2; ++ks)
#pragma unroll
            for (int mt = 0; mt < 2; ++mt)
#pragma unroll
                for (int nt = 0; nt < 8; ++nt)
                    mma_bf16(acc[mt][nt], af[mt][ks], &bf[nt][ks * 2]);
        __syncthreads();
        if (c + 3 < 8) {
            uint32_t base = sb + ((c + 3) & 3) * ASTG;
            cp16(base + row * ROWB + sg * 16,       gA + (size_t)row * 512 + (size_t)(c + 3) * 64 + sg * 16);
            cp16(base + row * ROWB + (sg + 1) * 16, gA + (size_t)row * 512 + (size_t)(c + 3) * 64 + (sg + 1) * 16);
        }
        CP_COMMIT();
    }
}

#define ACC_DECL  float acc[2][8][4]; \
    _Pragma("unroll") for (int _m = 0; _m < 2; ++_m) \
    _Pragma("unroll") for (int _n = 0; _n < 8; ++_n) \
    _Pragma("unroll") for (int _q = 0; _q < 4; ++_q) acc[_m][_n][_q] = 0.0f;

#define EPI_COORDS \
    const int lane = threadIdx.x & 31, wid = threadIdx.x >> 5; \
    const int wr = wid & 3, wc = wid >> 2; \
    const int rowL = wr * 32 + (lane >> 2); \
    const int colL = wc * 64 + (lane & 3) * 2; \
    (void)wr; (void)wc;

// ---------------- K0: merged pre-pass: x transpose + PE transpose + weight conv + zero colsum ----
// grid 1340 blocks: [0,1024) xt, [1024,1280) pet, [1280,1340) weights/zero
__device__ __forceinline__ void conv4(const float* s, __nv_bfloat16* d, int i) {
    float4 v = *(const float4*)(s + i);
    *(uint32_t*)(d + i)     = bf2(v.x, v.y);
    *(uint32_t*)(d + i + 2) = bf2(v.z, v.w);
}
__global__ __launch_bounds__(256) void k_pre(
    const float* __restrict__ x, const float* __restrict__ PE,
    const float* __restrict__ W1, const float* __restrict__ W2, const float* __restrict__ WV,
    const float* __restrict__ WQ, const float* __restrict__ WK)
{
    __shared__ float ts[32][129];
    const int tid = threadIdx.x;
    const int gb = blockIdx.x;

    if (gb < 1024) {
        // ---- x [b][c][j] fp32 -> x_t [b][j][c] bf16 ----
        const int jt = (gb & 31) * 128, ct = ((gb >> 5) & 7) * 32, b = gb >> 8;
#pragma unroll
        for (int p = 0; p < 4; ++p) {
            int c = (tid >> 5) + p * 8;
            int j = (tid & 31) * 4;
            float4 v = *(const float4*)(x + ((size_t)b * CDIM + ct + c) * NTOK + jt + j);
            ts[c][j] = v.x; ts[c][j+1] = v.y; ts[c][j+2] = v.z; ts[c][j+3] = v.w;
        }
        __syncthreads();
#pragma unroll
        for (int p = 0; p < 8; ++p) {
            int idx = tid + p * 256;
            int j = idx >> 4, cp = idx & 15;
            *(uint32_t*)(g_xt + ((size_t)b * NTOK + jt + j) * CDIM + ct + cp * 2)
                = bf2(ts[cp * 2][j], ts[cp * 2 + 1][j]);
        }
    } else if (gb < 1280) {
        // ---- PE [d][i] -> PEt [i][d] fp32 (32x32 tile) ----
        const int blk = gb - 1024;
        const int it = (blk & 127) * 32, dt = (blk >> 7) * 32;
        const int r = tid >> 5, c = tid & 31;
        float (*t2)[33] = (float(*)[33])ts;
#pragma unroll
        for (int p = 0; p < 4; ++p)
            t2[r + p * 8][c] = PE[(size_t)(dt + r + p * 8) * NTOK + it + c];
        __syncthreads();
#pragma unroll
        for (int p = 0; p < 4; ++p)
            g_pet[(size_t)(it + r + p * 8) * QKD + dt + c] = t2[c][r + p * 8];
    } else {
        const int blk = gb - 1280;
        if (blk < 16) {
            int base = blk * 4096;
#pragma unroll
            for (int p = 0; p < 4; ++p) conv4(W1, g_W1b, base + p * 1024 + tid * 4);
        } else if (blk < 32) {
            int base = (blk - 16) * 4096;
#pragma unroll
            for (int p = 0; p < 4; ++p) conv4(W2, g_W2b, base + p * 1024 + tid * 4);
        } else if (blk < 48) {
            int base = (blk - 32) * 4096;
#pragma unroll
            for (int p = 0; p < 4; ++p) conv4(WV, g_WVb, base + p * 1024 + tid * 4);
        } else if (blk < 56) {
            int base = (blk - 48) * 4096;
#pragma unroll
            for (int p = 0; p < 4; ++p) {
                int i = base + p * 1024 + tid * 4;
                const float* s = (i < QKD * CDIM) ? (WQ + i) : (WK + i - QKD * CDIM);
                float4 v = *(const float4*)s;
                *(uint32_t*)(g_WQKb + i)     = bf2(v.x, v.y);
                *(uint32_t*)(g_WQKb + i + 2) = bf2(v.z, v.w);
            }
        } else {
            int base = (blk - 56) * 4096;
#pragma unroll
            for (int p = 0; p < 4; ++p)
                *(float4*)(g_cs + base + p * 1024 + tid * 4) = make_float4(0.f, 0.f, 0.f, 0.f);
        }
    }
}

// ---------------- K1: QK projection; Q pre-scaled by QK_SCL ----------------
__global__ __launch_bounds__(256, 2) void k_projqk_w(
    const float* __restrict__ bQ, const float* __restrict__ bK)
{
    extern __shared__ char smem[];
    const int i0 = blockIdx.x * 128, b = blockIdx.y;
    ACC_DECL;
    gemm_main<8, 4, false>((const char*)(g_xt + ((size_t)b * NTOK + i0) * CDIM), 512,
                           (const char*)g_WQKb, 512, smem, acc);
    EPI_COORDS;
    const bool isQ = (wc == 0);
    const float scl = isQ ? QK_SCL : 1.0f;
    __nv_bfloat16* dst = (isQ ? g_qb : g_kb) + (size_t)b * NTOK * QKD;
#pragma unroll
    for (int nt = 0; nt < 8; ++nt) {
        int d = (lane & 3) * 2 + nt * 8;
        float b0 = isQ ? bQ[d]     : bK[d];
        float b1 = isQ ? bQ[d + 1] : bK[d + 1];
#pragma unroll
        for (int mt = 0; mt < 2; ++mt)
#pragma unroll
            for (int h = 0; h < 2; ++h) {
                int row = i0 + rowL + mt * 16 + h * 8;
                float2 pe = *(const float2*)(g_pet + (size_t)row * QKD + d);
                *(uint32_t*)(dst + (size_t)row * QKD + d)
                    = bf2((acc[mt][nt][h*2] + b0 + pe.x) * scl,
                          (acc[mt][nt][h*2+1] + b1 + pe.y) * scl);
            }
    }
}

// ---------------- K2: QK^T mma + exp -> e4m3 E (smem-staged coalesced) + colsum ----------------
// grid (32 j, 32 i, 4 b). Q pre-scaled, so E = 2^(acc).
#define EST8  144   /* staging row stride in bytes: 16B-aligned; rows 4 banks apart */
__global__ __launch_bounds__(256, 2) void k_qkt_w()
{
    extern __shared__ char smem[];
    const int j0 = blockIdx.x * 128, i0 = blockIdx.y * 128, b = blockIdx.z;
    ACC_DECL;
    gemm_main<2, 2, false>((const char*)(g_qb + ((size_t)b * NTOK + i0) * QKD), 128,
                           (const char*)(g_kb + ((size_t)b * NTOK + j0) * QKD), 128,
                           smem, acc);
    EPI_COORDS;
    uint8_t* est = (uint8_t*)smem;     // 128 x 144B staging (18.4 KB)
    float cs[8][2];
#pragma unroll
    for (int nt = 0; nt < 8; ++nt) { cs[nt][0] = 0.f; cs[nt][1] = 0.f; }
#pragma unroll
    for (int mt = 0; mt < 2; ++mt)
#pragma unroll
        for (int nt = 0; nt < 8; ++nt) {
            int col = colL + nt * 8;                 // local col 0..127
#pragma unroll
            for (int h = 0; h < 2; ++h) {
                int row = rowL + mt * 16 + h * 8;    // local row 0..127
                uint32_t ee = ex2_bf16x2(bf2(acc[mt][nt][h*2], acc[mt][nt][h*2+1]));
                float e0 = __int_as_float(ee << 16);
                float e1 = __int_as_float(ee & 0xFFFF0000u);
                *(unsigned short*)(est + row * EST8 + col) = fp8x2(e0, e1);
                cs[nt][0] += e0;
                cs[nt][1] += e1;
            }
        }
    __syncthreads();
    {
        const int tid = threadIdx.x;
        uint8_t* ep = g_E8 + ((size_t)b * NTOK + i0) * NTOK + j0;
#pragma unroll
        for (int p = 0; p < 4; ++p) {
            int idx = tid + p * 256;
            int row = idx >> 3, seg = idx & 7;
            uint4 v = *(const uint4*)(est + row * EST8 + seg * 16);
            *(uint4*)(ep + (size_t)row * NTOK + seg * 16) = v;
        }
    }
#pragma unroll
    for (int nt = 0; nt < 8; ++nt)
#pragma unroll
        for (int p = 0; p < 2; ++p) {
            float v = cs[nt][p];
            v += __shfl_xor_sync(0xFFFFFFFFu, v, 4);
            v += __shfl_xor_sync(0xFFFFFFFFu, v, 8);
            v += __shfl_xor_sync(0xFFFFFFFFu, v, 16);
            cs[nt][p] = v;
        }
    float* sred = (float*)smem;
    __syncthreads();
    if (threadIdx.x < 128) sred[threadIdx.x] = 0.0f;
    __syncthreads();
    if ((lane >> 2) == 0) {
#pragma unroll
        for (int nt = 0; nt < 8; ++nt) {
            int cc = wc * 64 + (lane & 3) * 2 + nt * 8;
            atomicAdd(&sred[cc],     cs[nt][0]);
            atomicAdd(&sred[cc + 1], cs[nt][1]);
        }
    }
    __syncthreads();
    if (threadIdx.x < 128)
        atomicAdd(&g_cs[(size_t)b * NTOK + j0 + threadIdx.x], sred[threadIdx.x]);
}

// ---------------- K2b: w = 4096/colsum ----------------
__global__ __launch_bounds__(256) void k_wcalc()
{
    int idx = blockIdx.x * 256 + threadIdx.x;
    g_w[idx] = 4096.0f / g_cs[idx];
}

// ---------------- K3: V projection (epilogue *w[j]+bias -> e4m3 g_vb8) ----------------
__global__ __launch_bounds__(256, 2) void k_projv_w(const float* __restrict__ bV)
{
    extern __shared__ char smem[];
    const int j0 = blockIdx.x * 128, m0 = blockIdx.y * 128, b = blockIdx.z;
    ACC_DECL;
    gemm_main<8, 4, false>((const char*)(g_WVb + (size_t)m0 * CDIM), 512,
                           (const char*)(g_xt + ((size_t)b * NTOK + j0) * CDIM), 512,
                           smem, acc);
    EPI_COORDS;
#pragma unroll
    for (int mt = 0; mt < 2; ++mt)
#pragma unroll
        for (int h = 0; h < 2; ++h) {
            int row = m0 + rowL + mt * 16 + h * 8;
            float bb = bV[row];
#pragma unroll
            for (int nt = 0; nt < 8; ++nt) {
                int col = j0 + colL + nt * 8;
                float2 w2 = *(const float2*)(g_w + (size_t)b * NTOK + col);
                *(unsigned short*)(g_vb8 + ((size_t)b * CDIM + row) * NTOK + col)
                    = fp8x2((acc[mt][nt][h*2] + bb) * w2.x, (acc[mt][nt][h*2+1] + bb) * w2.y);
            }
        }
}

// ---------------- K4: AO = E @ Vb (fp8 mma, K=4096) -> bf16 ao[i][c] ----------------
__global__ __launch_bounds__(256) void k_av_w()
{
    extern __shared__ char smem[];
    const int n0 = blockIdx.x * 128, i0 = blockIdx.y * 128, b = blockIdx.z;
    ACC_DECL;
    gemm_main<64, 4, true>((const char*)(g_E8  + ((size_t)b * NTOK + i0) * NTOK), 4096,
                           (const char*)(g_vb8 + ((size_t)b * CDIM + n0) * NTOK), 4096,
                           smem, acc);
    EPI_COORDS;
#pragma unroll
    for (int mt = 0; mt < 2; ++mt)
#pragma unroll
        for (int nt = 0; nt < 8; ++nt) {
            int col = n0 + colL + nt * 8;
#pragma unroll
            for (int h = 0; h < 2; ++h) {
                int row = i0 + rowL + mt * 16 + h * 8;
                *(uint32_t*)(g_aob + ((size_t)b * NTOK + row) * CDIM + col)
                    = bf2(acc[mt][nt][h*2] * AV_SCL, acc[mt][nt][h*2+1] * AV_SCL);
            }
        }
}

// ---------------- K5: fused MLP: H = mish(AO@W1^T+b1) in smem; OUT = W2@H^T + b2 + x ----------------
// grid (32 iblk, 4 b), 256 thr. smem: ring (81920) + H (128 x 528B = 67584) = 149504 B
#define MLP_SMEM (SMEM4 + 128 * HROWB)
__global__ __launch_bounds__(256) void k_mlp_f(
    const float* __restrict__ b1, const float* __restrict__ b2,
    const float* __restrict__ x, float* __restrict__ out)
{
    extern __shared__ char smem[];
    char* ring = smem;
    __nv_bfloat16* Hs = (__nv_bfloat16*)(smem + SMEM4);
    const uint32_t hsb = smem_u32(Hs);
    const int i0 = blockIdx.x * 128, b = blockIdx.y;
    EPI_COORDS;

    // ---- phase 1: H tile (128 i x 256 o) -> smem ----
#pragma unroll 1
    for (int ob = 0; ob < 2; ++ob) {
        ACC_DECL;
        gemm_main<8, 4, false>((const char*)(g_aob + ((size_t)b * NTOK + i0) * CDIM), 512,
                               (const char*)(g_W1b + (size_t)ob * 128 * CDIM), 512, ring, acc);
#pragma unroll
        for (int nt = 0; nt < 8; ++nt) {
            int col = ob * 128 + colL + nt * 8;
            float bb0 = b1[col], bb1 = b1[col + 1];
#pragma unroll
            for (int mt = 0; mt < 2; ++mt)
#pragma unroll
                for (int h = 0; h < 2; ++h) {
                    int row = rowL + mt * 16 + h * 8;      // local i row
                    *(uint32_t*)((char*)Hs + row * HROWB + col * 2)
                        = bf2(mishf(acc[mt][nt][h*2] + bb0), mishf(acc[mt][nt][h*2+1] + bb1));
                }
        }
        __syncthreads();   // H writes visible; ring reusable
    }

    // ---- phase 2: OUT (256 c x 128 i) from W2 (streamed) x H (smem) ----
#pragma unroll 1
    for (int cb = 0; cb < 2; ++cb) {
        ACC_DECL;
        gemm_w2((const char*)(g_W2b + (size_t)cb * 128 * CDIM), hsb, ring, acc);
#pragma unroll
        for (int mt = 0; mt < 2; ++mt)
#pragma unroll
            for (int h = 0; h < 2; ++h) {
                int row = cb * 128 + rowL + mt * 16 + h * 8;   // channel c
                float bb = b2[row];
                size_t base = ((size_t)b * CDIM + row) * NTOK;
#pragma unroll
                for (int nt = 0; nt < 8; ++nt) {
                    int col = i0 + colL + nt * 8;
                    float2 xv = *(const float2*)(x + base + col);
                    *(float2*)(out + base + col)
                        = make_float2(acc[mt][nt][h*2]   + bb + xv.x,
                                      acc[mt][nt][h*2+1] + bb + xv.y);
                }
            }
        __syncthreads();   // ring reusable for next cb
    }
}

// ---------------- launch ----------------
extern "C" void kernel_launch(void* const* d_in, const int* in_sizes, int n_in,
                              void* d_out, int out_size)
{
    (void)in_sizes; (void)n_in; (void)out_size;
    const float* x  = (const float*)d_in[0];
    const float* WQ = (const float*)d_in[1];
    const float* bQ = (const float*)d_in[2];
    const float* WK = (const float*)d_in[3];
    const float* bK = (const float*)d_in[4];
    const float* WV = (const float*)d_in[5];
    const float* bV = (const float*)d_in[6];
    const float* PE = (const float*)d_in[7];
    const float* W1 = (const float*)d_in[8];
    const float* b1 = (const float*)d_in[9];
    const float* W2 = (const float*)d_in[10];
    const float* b2 = (const float*)d_in[11];
    float* out = (float*)d_out;

    cudaFuncSetAttribute(k_projqk_w, cudaFuncAttributeMaxDynamicSharedMemorySize, SMEM4);
    cudaFuncSetAttribute(k_qkt_w,    cudaFuncAttributeMaxDynamicSharedMemorySize, SMEM2);
    cudaFuncSetAttribute(k_projv_w,  cudaFuncAttributeMaxDynamicSharedMemorySize, SMEM4);
    cudaFuncSetAttribute(k_av_w,     cudaFuncAttributeMaxDynamicSharedMemorySize, SMEM4);
    cudaFuncSetAttribute(k_mlp_f,    cudaFuncAttributeMaxDynamicSharedMemorySize, MLP_SMEM);

    // av is launch #6 -> lands in ncu's fixed capture slot (-s 5 -c 1)
    k_pre     <<<dim3(1340),        256>>>(x, PE, W1, W2, WV, WQ, WK);
    k_projqk_w<<<dim3(32, NB),      256, SMEM4>>>(bQ, bK);
    k_qkt_w   <<<dim3(32, 32, NB),  256, SMEM2>>>();
    k_wcalc   <<<dim3(64),          256>>>();
    k_projv_w <<<dim3(32, 2, NB),   256, SMEM4>>>(bV);
    k_av_w    <<<dim3(2, 32, NB),   256, SMEM4>>>();
    k_mlp_f   <<<dim3(32, NB),      256, MLP_SMEM>>>(b1, b2, x, out);
}

// round 16
// speedup vs baseline: 1.0183x; 1.0047x over previous
#include <cuda_runtime.h>
#include <cuda_bf16.h>
#include <math.h>
#include <cstdint>

#define NTOK 4096
#define CDIM 256
#define QKD  64
#define NB   4

typedef unsigned long long u64;

// ---------------- scratch (device globals) ----------------
__device__ __align__(256) __nv_bfloat16 g_xt  [(size_t)NB * NTOK * CDIM];  // [b][j][c] bf16
__device__ __align__(256) float         g_pet [(size_t)NTOK * QKD];        // PE^T [i][d] fp32
__device__ __align__(256) __nv_bfloat16 g_qb  [(size_t)NB * NTOK * QKD];   // [b][i][d] (pre-scaled)
__device__ __align__(256) __nv_bfloat16 g_kb  [(size_t)NB * NTOK * QKD];   // [b][j][d]
__device__ __align__(256) uint8_t       g_E8  [(size_t)NB * NTOK * NTOK];  // [b][i][j] e4m3 exp(S)
__device__ __align__(256) uint8_t       g_vb8 [(size_t)NB * CDIM * NTOK];  // [b][c][j] e4m3 (V+b)*w*4096
__device__ __align__(256) float         g_cs  [NB * NTOK];                 // column sums (atomic)
__device__ __align__(256) __nv_bfloat16 g_aob [(size_t)NB * NTOK * CDIM];  // [b][i][c]
__device__ __align__(256) __nv_bfloat16 g_W1b [CDIM * CDIM];
__device__ __align__(256) __nv_bfloat16 g_W2b [CDIM * CDIM];
__device__ __align__(256) __nv_bfloat16 g_WVb [CDIM * CDIM];
__device__ __align__(256) __nv_bfloat16 g_WQKb[2 * QKD * CDIM];

// ---------------- PTX helpers ----------------
__device__ __forceinline__ uint32_t smem_u32(const void* p) {
    uint32_t a;
    asm("{ .reg .u64 t; cvta.to.shared.u64 t, %1; cvt.u32.u64 %0, t; }" : "=r"(a) : "l"(p));
    return a;
}
#define CP_COMMIT()  asm volatile("cp.async.commit_group;" ::: "memory")
template <int N>
__device__ __forceinline__ void cp_wait() {
    asm volatile("cp.async.wait_group %0;" :: "n"(N) : "memory");
}
__device__ __forceinline__ void cp16(uint32_t d, const void* s) {
    asm volatile("cp.async.cg.shared.global [%0], [%1], 16;" :: "r"(d), "l"(s) : "memory");
}
__device__ __forceinline__ void ldsm4(uint32_t r[4], uint32_t a) {
    asm volatile("ldmatrix.sync.aligned.m8n8.x4.shared.b16 {%0,%1,%2,%3}, [%4];"
                 : "=r"(r[0]), "=r"(r[1]), "=r"(r[2]), "=r"(r[3]) : "r"(a));
}
__device__ __forceinline__ void mma_bf16(float c[4], const uint32_t a[4], const uint32_t b[2]) {
    asm volatile("mma.sync.aligned.m16n8k16.row.col.f32.bf16.bf16.f32 "
                 "{%0,%1,%2,%3}, {%4,%5,%6,%7}, {%8,%9}, {%0,%1,%2,%3};"
                 : "+f"(c[0]), "+f"(c[1]), "+f"(c[2]), "+f"(c[3])
                 : "r"(a[0]), "r"(a[1]), "r"(a[2]), "r"(a[3]), "r"(b[0]), "r"(b[1]));
}
__device__ __forceinline__ void mma_fp8(float c[4], const uint32_t a[4], const uint32_t b[2]) {
    asm volatile("mma.sync.aligned.m16n8k32.row.col.f32.e4m3.e4m3.f32 "
                 "{%0,%1,%2,%3}, {%4,%5,%6,%7}, {%8,%9}, {%0,%1,%2,%3};"
                 : "+f"(c[0]), "+f"(c[1]), "+f"(c[2]), "+f"(c[3])
                 : "r"(a[0]), "r"(a[1]), "r"(a[2]), "r"(a[3]), "r"(b[0]), "r"(b[1]));
}
__device__ __forceinline__ uint32_t bf2(float x, float y) {
    __nv_bfloat162 h = __floats2bfloat162_rn(x, y);
    return *(uint32_t*)&h;
}
__device__ __forceinline__ unsigned short fp8x2(float lo, float hi) {
    unsigned short r;
    asm("cvt.rn.satfinite.e4m3x2.f32 %0, %1, %2;" : "=h"(r) : "f"(hi), "f"(lo));
    return r;
}
__device__ __forceinline__ uint32_t ex2_bf16x2(uint32_t a) {
    uint32_t d; asm("ex2.approx.ftz.bf16x2 %0, %1;" : "=r"(d) : "r"(a)); return d;
}
__device__ __forceinline__ float ex2f(float x) {
    float y; asm("ex2.approx.f32 %0, %1;" : "=f"(y) : "f"(x)); return y;
}
__device__ __forceinline__ float lg2f_a(float x) {
    float y; asm("lg2.approx.f32 %0, %1;" : "=f"(y) : "f"(x)); return y;
}
__device__ __forceinline__ float tanh_a(float x) {
    float y; asm("tanh.approx.f32 %0, %1;" : "=f"(y) : "f"(x)); return y;
}
__device__ __forceinline__ float mishf(float v) {
    float t  = ex2f(v * 1.4426950408889634f);
    float sp = lg2f_a(1.0f + t) * 0.6931471805599453f;
    return v * tanh_a(sp);
}
#define QK_SCL 0.18033688011112042f   /* 0.125 * log2(e), folded into Q */
#define AV_SCL 0.000244140625f        /* 1/4096, undoes Vb rescale */

// ================= shared warp-MMA GEMM mainloop =================
// CTA: 256 thr (8 warps, 4 M x 2 N), tile 128(M) x 128(N).
// K-chunk = 64 bytes/row: 32 bf16 or 64 e4m3.
#define ROWB   80
#define SBOFF  (128 * ROWB)
#define STG    (2 * 128 * ROWB)
#define SMEM4  (4 * STG)
#define SMEM2  (2 * STG)

template <int NCH, int NST, bool FP8>
__device__ __forceinline__ void gemm_main(const char* __restrict__ gA, size_t lda,
                                          const char* __restrict__ gB, size_t ldb,
                                          char* smem, float acc[2][8][4])
{
    const int tid  = threadIdx.x;
    const int lane = tid & 31, wid = tid >> 5;
    const int wr = wid & 3, wc = wid >> 2;
    const uint32_t sb = smem_u32(smem);
    const int r0  = tid >> 2;
    const int seg = tid & 3;

    const uint32_t aOff = (uint32_t)((wr * 32 + (lane & 15)) * ROWB + (lane >> 4) * 16);
    const uint32_t bOff = (uint32_t)(SBOFF + (wc * 64 + (lane & 7)) * ROWB + ((lane >> 3) & 3) * 16);

#pragma unroll
    for (int s = 0; s < NST - 1; ++s) {
        if (s < NCH) {
            uint32_t base = sb + (s % NST) * STG;
#pragma unroll
            for (int h = 0; h < 2; ++h) {
                int row = r0 + h * 64;
                cp16(base + row * ROWB + seg * 16, gA + (size_t)row * lda + (size_t)s * 64 + seg * 16);
                cp16(base + SBOFF + row * ROWB + seg * 16, gB + (size_t)row * ldb + (size_t)s * 64 + seg * 16);
            }
        }
        CP_COMMIT();
    }
    for (int c = 0; c < NCH; ++c) {
        cp_wait<NST - 2>();
        __syncthreads();
        const uint32_t st = sb + (c % NST) * STG;
        uint32_t af[2][2][4], bf[8][4];
#pragma unroll
        for (int mt = 0; mt < 2; ++mt)
#pragma unroll
            for (int ks = 0; ks < 2; ++ks)
                ldsm4(af[mt][ks], st + aOff + mt * (16 * ROWB) + ks * 32);
#pragma unroll
        for (int nt = 0; nt < 8; ++nt)
            ldsm4(bf[nt], st + bOff + nt * (8 * ROWB));
#pragma unroll
        for (int ks = 0; ks < 2; ++ks)
#pragma unroll
            for (int mt = 0; mt < 2; ++mt)
#pragma unroll
                for (int nt = 0; nt < 8; ++nt) {
                    if (FP8) mma_fp8(acc[mt][nt], af[mt][ks], &bf[nt][ks * 2]);
                    else     mma_bf16(acc[mt][nt], af[mt][ks], &bf[nt][ks * 2]);
                }
        __syncthreads();
        if (c + NST - 1 < NCH) {
            uint32_t base = sb + ((c + NST - 1) % NST) * STG;
#pragma unroll
            for (int h = 0; h < 2; ++h) {
                int row = r0 + h * 64;
                cp16(base + row * ROWB + seg * 16, gA + (size_t)row * lda + (size_t)(c + NST - 1) * 64 + seg * 16);
                cp16(base + SBOFF + row * ROWB + seg * 16, gB + (size_t)row * ldb + (size_t)(c + NST - 1) * 64 + seg * 16);
            }
        }
        CP_COMMIT();
    }
}

// ---- phase-2 mainloop for fused MLP: A streamed via A-only ring, B from persistent smem H ----
// K = 256 (o). A-ring stage = 64 B/row = 32 k per chunk -> 8 chunks. H offset per chunk = 64 B.
#define HROWB 528                       /* bytes per H row: 256 bf16 data (512B) + 16B pad */
#define ASTG  (128 * ROWB)              /* A-only stage = 10240 B */
__device__ __forceinline__ void gemm_w2(const char* __restrict__ gA,
                                        uint32_t hsb, char* ring, float acc[2][8][4])
{
    const int tid  = threadIdx.x;
    const int lane = tid & 31, wid = tid >> 5;
    const int wr = wid & 3, wc = wid >> 2;
    const uint32_t sb = smem_u32(ring);
    const int row = tid >> 1, sg = (tid & 1) * 2;

    const uint32_t aOff  = (uint32_t)((wr * 32 + (lane & 15)) * ROWB + (lane >> 4) * 16);
    const uint32_t bOffH = (uint32_t)((wc * 64 + (lane & 7)) * HROWB + ((lane >> 3) & 3) * 16);

#pragma unroll
    for (int s = 0; s < 3; ++s) {
        uint32_t base = sb + s * ASTG;
        cp16(base + row * ROWB + sg * 16,       gA + (size_t)row * 512 + (size_t)s * 64 + sg * 16);
        cp16(base + row * ROWB + (sg + 1) * 16, gA + (size_t)row * 512 + (size_t)s * 64 + (sg + 1) * 16);
        CP_COMMIT();
    }
    for (int c = 0; c < 8; ++c) {
        cp_wait<2>();
        __syncthreads();
        const uint32_t st = sb + (c & 3) * ASTG;
        uint32_t af[2][2][4], bf[8][4];
#pragma unroll
        for (int mt = 0; mt < 2; ++mt)
#pragma unroll
            for (int ks = 0; ks < 2; ++ks)
                ldsm4(af[mt][ks], st + aOff + mt * (16 * ROWB) + ks * 32);
#pragma unroll
        for (int nt = 0; nt < 8; ++nt)
            ldsm4(bf[nt], hsb + bOffH + nt * (8 * HROWB) + c * 64);
#pragma unroll
        for (int ks = 0; ks < 2; ++ks)
#pragma unroll
            for (int mt = 0; mt < 2; ++mt)
#pragma unroll
                for (int nt = 0; nt < 8; ++nt)
                    mma_bf16(acc[mt][nt], af[mt][ks], &bf[nt][ks * 2]);
        __syncthreads();
        if (c + 3 < 8) {
            uint32_t base = sb + ((c + 3) & 3) * ASTG;
            cp16(base + row * ROWB + sg * 16,       gA + (size_t)row * 512 + (size_t)(c + 3) * 64 + sg * 16);
            cp16(base + row * ROWB + (sg + 1) * 16, gA + (size_t)row * 512 + (size_t)(c + 3) * 64 + (sg + 1) * 16);
        }
        CP_COMMIT();
    }
}

#define ACC_DECL  float acc[2][8][4]; \
    _Pragma("unroll") for (int _m = 0; _m < 2; ++_m) \
    _Pragma("unroll") for (int _n = 0; _n < 8; ++_n) \
    _Pragma("unroll") for (int _q = 0; _q < 4; ++_q) acc[_m][_n][_q] = 0.0f;

#define EPI_COORDS \
    const int lane = threadIdx.x & 31, wid = threadIdx.x >> 5; \
    const int wr = wid & 3, wc = wid >> 2; \
    const int rowL = wr * 32 + (lane >> 2); \
    const int colL = wc * 64 + (lane & 3) * 2; \
    (void)wr; (void)wc;

// ---------------- K0: merged pre-pass: x transpose + PE transpose + weight conv + zero colsum ----
// grid 1340 blocks: [0,1024) xt, [1024,1280) pet, [1280,1340) weights/zero
__device__ __forceinline__ void conv4(const float* s, __nv_bfloat16* d, int i) {
    float4 v = *(const float4*)(s + i);
    *(uint32_t*)(d + i)     = bf2(v.x, v.y);
    *(uint32_t*)(d + i + 2) = bf2(v.z, v.w);
}
__global__ __launch_bounds__(256) void k_pre(
    const float* __restrict__ x, const float* __restrict__ PE,
    const float* __restrict__ W1, const float* __restrict__ W2, const float* __restrict__ WV,
    const float* __restrict__ WQ, const float* __restrict__ WK)
{
    __shared__ float ts[32][129];
    const int tid = threadIdx.x;
    const int gb = blockIdx.x;

    if (gb < 1024) {
        // ---- x [b][c][j] fp32 -> x_t [b][j][c] bf16 ----
        const int jt = (gb & 31) * 128, ct = ((gb >> 5) & 7) * 32, b = gb >> 8;
#pragma unroll
        for (int p = 0; p < 4; ++p) {
            int c = (tid >> 5) + p * 8;
            int j = (tid & 31) * 4;
            float4 v = *(const float4*)(x + ((size_t)b * CDIM + ct + c) * NTOK + jt + j);
            ts[c][j] = v.x; ts[c][j+1] = v.y; ts[c][j+2] = v.z; ts[c][j+3] = v.w;
        }
        __syncthreads();
#pragma unroll
        for (int p = 0; p < 8; ++p) {
            int idx = tid + p * 256;
            int j = idx >> 4, cp = idx & 15;
            *(uint32_t*)(g_xt + ((size_t)b * NTOK + jt + j) * CDIM + ct + cp * 2)
                = bf2(ts[cp * 2][j], ts[cp * 2 + 1][j]);
        }
    } else if (gb < 1280) {
        // ---- PE [d][i] -> PEt [i][d] fp32 (32x32 tile) ----
        const int blk = gb - 1024;
        const int it = (blk & 127) * 32, dt = (blk >> 7) * 32;
        const int r = tid >> 5, c = tid & 31;
        float (*t2)[33] = (float(*)[33])ts;
#pragma unroll
        for (int p = 0; p < 4; ++p)
            t2[r + p * 8][c] = PE[(size_t)(dt + r + p * 8) * NTOK + it + c];
        __syncthreads();
#pragma unroll
        for (int p = 0; p < 4; ++p)
            g_pet[(size_t)(it + r + p * 8) * QKD + dt + c] = t2[c][r + p * 8];
    } else {
        const int blk = gb - 1280;
        if (blk < 16) {
            int base = blk * 4096;
#pragma unroll
            for (int p = 0; p < 4; ++p) conv4(W1, g_W1b, base + p * 1024 + tid * 4);
        } else if (blk < 32) {
            int base = (blk - 16) * 4096;
#pragma unroll
            for (int p = 0; p < 4; ++p) conv4(W2, g_W2b, base + p * 1024 + tid * 4);
        } else if (blk < 48) {
            int base = (blk - 32) * 4096;
#pragma unroll
            for (int p = 0; p < 4; ++p) conv4(WV, g_WVb, base + p * 1024 + tid * 4);
        } else if (blk < 56) {
            int base = (blk - 48) * 4096;
#pragma unroll
            for (int p = 0; p < 4; ++p) {
                int i = base + p * 1024 + tid * 4;
                const float* s = (i < QKD * CDIM) ? (WQ + i) : (WK + i - QKD * CDIM);
                float4 v = *(const float4*)s;
                *(uint32_t*)(g_WQKb + i)     = bf2(v.x, v.y);
                *(uint32_t*)(g_WQKb + i + 2) = bf2(v.z, v.w);
            }
        } else {
            int base = (blk - 56) * 4096;
#pragma unroll
            for (int p = 0; p < 4; ++p)
                *(float4*)(g_cs + base + p * 1024 + tid * 4) = make_float4(0.f, 0.f, 0.f, 0.f);
        }
    }
}

// ---------------- K1: QK projection; Q pre-scaled by QK_SCL ----------------
__global__ __launch_bounds__(256, 2) void k_projqk_w(
    const float* __restrict__ bQ, const float* __restrict__ bK)
{
    extern __shared__ char smem[];
    const int i0 = blockIdx.x * 128, b = blockIdx.y;
    ACC_DECL;
    gemm_main<8, 4, false>((const char*)(g_xt + ((size_t)b * NTOK + i0) * CDIM), 512,
                           (const char*)g_WQKb, 512, smem, acc);
    EPI_COORDS;
    const bool isQ = (wc == 0);
    const float scl = isQ ? QK_SCL : 1.0f;
    __nv_bfloat16* dst = (isQ ? g_qb : g_kb) + (size_t)b * NTOK * QKD;
#pragma unroll
    for (int nt = 0; nt < 8; ++nt) {
        int d = (lane & 3) * 2 + nt * 8;
        float b0 = isQ ? bQ[d]     : bK[d];
        float b1 = isQ ? bQ[d + 1] : bK[d + 1];
#pragma unroll
        for (int mt = 0; mt < 2; ++mt)
#pragma unroll
            for (int h = 0; h < 2; ++h) {
                int row = i0 + rowL + mt * 16 + h * 8;
                float2 pe = *(const float2*)(g_pet + (size_t)row * QKD + d);
                *(uint32_t*)(dst + (size_t)row * QKD + d)
                    = bf2((acc[mt][nt][h*2] + b0 + pe.x) * scl,
                          (acc[mt][nt][h*2+1] + b1 + pe.y) * scl);
            }
    }
}

// ---------------- K2: QK^T mma + exp -> e4m3 E (smem-staged coalesced) + colsum ----------------
// grid (32 j, 32 i, 4 b). Q pre-scaled, so E = 2^(acc).
#define EST8  144   /* staging row stride in bytes: 16B-aligned; rows 4 banks apart */
__global__ __launch_bounds__(256, 2) void k_qkt_w()
{
    extern __shared__ char smem[];
    const int j0 = blockIdx.x * 128, i0 = blockIdx.y * 128, b = blockIdx.z;
    ACC_DECL;
    gemm_main<2, 2, false>((const char*)(g_qb + ((size_t)b * NTOK + i0) * QKD), 128,
                           (const char*)(g_kb + ((size_t)b * NTOK + j0) * QKD), 128,
                           smem, acc);
    EPI_COORDS;
    uint8_t* est = (uint8_t*)smem;     // 128 x 144B staging (18.4 KB)
    float cs[8][2];
#pragma unroll
    for (int nt = 0; nt < 8; ++nt) { cs[nt][0] = 0.f; cs[nt][1] = 0.f; }
#pragma unroll
    for (int mt = 0; mt < 2; ++mt)
#pragma unroll
        for (int nt = 0; nt < 8; ++nt) {
            int col = colL + nt * 8;                 // local col 0..127
#pragma unroll
            for (int h = 0; h < 2; ++h) {
                int row = rowL + mt * 16 + h * 8;    // local row 0..127
                uint32_t ee = ex2_bf16x2(bf2(acc[mt][nt][h*2], acc[mt][nt][h*2+1]));
                float e0 = __int_as_float(ee << 16);
                float e1 = __int_as_float(ee & 0xFFFF0000u);
                *(unsigned short*)(est + row * EST8 + col) = fp8x2(e0, e1);
                cs[nt][0] += e0;
                cs[nt][1] += e1;
            }
        }
    __syncthreads();
    {
        const int tid = threadIdx.x;
        uint8_t* ep = g_E8 + ((size_t)b * NTOK + i0) * NTOK + j0;
#pragma unroll
        for (int p = 0; p < 4; ++p) {
            int idx = tid + p * 256;
            int row = idx >> 3, seg = idx & 7;
            uint4 v = *(const uint4*)(est + row * EST8 + seg * 16);
            *(uint4*)(ep + (size_t)row * NTOK + seg * 16) = v;
        }
    }
#pragma unroll
    for (int nt = 0; nt < 8; ++nt)
#pragma unroll
        for (int p = 0; p < 2; ++p) {
            float v = cs[nt][p];
            v += __shfl_xor_sync(0xFFFFFFFFu, v, 4);
            v += __shfl_xor_sync(0xFFFFFFFFu, v, 8);
            v += __shfl_xor_sync(0xFFFFFFFFu, v, 16);
            cs[nt][p] = v;
        }
    float* sred = (float*)smem;
    __syncthreads();
    if (threadIdx.x < 128) sred[threadIdx.x] = 0.0f;
    __syncthreads();
    if ((lane >> 2) == 0) {
#pragma unroll
        for (int nt = 0; nt < 8; ++nt) {
            int cc = wc * 64 + (lane & 3) * 2 + nt * 8;
            atomicAdd(&sred[cc],     cs[nt][0]);
            atomicAdd(&sred[cc + 1], cs[nt][1]);
        }
    }
    __syncthreads();
    if (threadIdx.x < 128)
        atomicAdd(&g_cs[(size_t)b * NTOK + j0 + threadIdx.x], sred[threadIdx.x]);
}

// ---------------- K3: V projection (epilogue: w = 4096/colsum inline, *w+bias -> e4m3) ----------------
__global__ __launch_bounds__(256, 2) void k_projv_w(const float* __restrict__ bV)
{
    extern __shared__ char smem[];
    const int j0 = blockIdx.x * 128, m0 = blockIdx.y * 128, b = blockIdx.z;
    ACC_DECL;
    gemm_main<8, 4, false>((const char*)(g_WVb + (size_t)m0 * CDIM), 512,
                           (const char*)(g_xt + ((size_t)b * NTOK + j0) * CDIM), 512,
                           smem, acc);
    EPI_COORDS;
    // per-thread w values (16 columns), computed once: w = 4096/colsum (IEEE div, same as old k_wcalc)
    float wv[8][2];
#pragma unroll
    for (int nt = 0; nt < 8; ++nt) {
        int col = j0 + colL + nt * 8;
        float2 c2 = *(const float2*)(g_cs + (size_t)b * NTOK + col);
        wv[nt][0] = 4096.0f / c2.x;
        wv[nt][1] = 4096.0f / c2.y;
    }
#pragma unroll
    for (int mt = 0; mt < 2; ++mt)
#pragma unroll
        for (int h = 0; h < 2; ++h) {
            int row = m0 + rowL + mt * 16 + h * 8;
            float bb = bV[row];
#pragma unroll
            for (int nt = 0; nt < 8; ++nt) {
                int col = j0 + colL + nt * 8;
                *(unsigned short*)(g_vb8 + ((size_t)b * CDIM + row) * NTOK + col)
                    = fp8x2((acc[mt][nt][h*2] + bb) * wv[nt][0],
                            (acc[mt][nt][h*2+1] + bb) * wv[nt][1]);
            }
        }
}

// ---------------- K4: AO = E @ Vb (fp8 mma, K=4096) -> bf16 ao[i][c] ----------------
__global__ __launch_bounds__(256) void k_av_w()
{
    extern __shared__ char smem[];
    const int n0 = blockIdx.x * 128, i0 = blockIdx.y * 128, b = blockIdx.z;
    ACC_DECL;
    gemm_main<64, 4, true>((const char*)(g_E8  + ((size_t)b * NTOK + i0) * NTOK), 4096,
                           (const char*)(g_vb8 + ((size_t)b * CDIM + n0) * NTOK), 4096,
                           smem, acc);
    EPI_COORDS;
#pragma unroll
    for (int mt = 0; mt < 2; ++mt)
#pragma unroll
        for (int nt = 0; nt < 8; ++nt) {
            int col = n0 + colL + nt * 8;
#pragma unroll
            for (int h = 0; h < 2; ++h) {
                int row = i0 + rowL + mt * 16 + h * 8;
                *(uint32_t*)(g_aob + ((size_t)b * NTOK + row) * CDIM + col)
                    = bf2(acc[mt][nt][h*2] * AV_SCL, acc[mt][nt][h*2+1] * AV_SCL);
            }
        }
}

// ---------------- K5: fused MLP: H = mish(AO@W1^T+b1) in smem; OUT = W2@H^T + b2 + x ----------------
// grid (32 iblk, 4 b), 256 thr. smem: ring (81920) + H (128 x 528B = 67584) = 149504 B
#define MLP_SMEM (SMEM4 + 128 * HROWB)
__global__ __launch_bounds__(256) void k_mlp_f(
    const float* __restrict__ b1, const float* __restrict__ b2,
    const float* __restrict__ x, float* __restrict__ out)
{
    extern __shared__ char smem[];
    char* ring = smem;
    __nv_bfloat16* Hs = (__nv_bfloat16*)(smem + SMEM4);
    const uint32_t hsb = smem_u32(Hs);
    const int i0 = blockIdx.x * 128, b = blockIdx.y;
    EPI_COORDS;

    // ---- phase 1: H tile (128 i x 256 o) -> smem ----
#pragma unroll 1
    for (int ob = 0; ob < 2; ++ob) {
        ACC_DECL;
        gemm_main<8, 4, false>((const char*)(g_aob + ((size_t)b * NTOK + i0) * CDIM), 512,
                               (const char*)(g_W1b + (size_t)ob * 128 * CDIM), 512, ring, acc);
#pragma unroll
        for (int nt = 0; nt < 8; ++nt) {
            int col = ob * 128 + colL + nt * 8;
            float bb0 = b1[col], bb1 = b1[col + 1];
#pragma unroll
            for (int mt = 0; mt < 2; ++mt)
#pragma unroll
                for (int h = 0; h < 2; ++h) {
                    int row = rowL + mt * 16 + h * 8;      // local i row
                    *(uint32_t*)((char*)Hs + row * HROWB + col * 2)
                        = bf2(mishf(acc[mt][nt][h*2] + bb0), mishf(acc[mt][nt][h*2+1] + bb1));
                }
        }
        __syncthreads();   // H writes visible; ring reusable
    }

    // ---- phase 2: OUT (256 c x 128 i) from W2 (streamed) x H (smem) ----
#pragma unroll 1
    for (int cb = 0; cb < 2; ++cb) {
        ACC_DECL;
        gemm_w2((const char*)(g_W2b + (size_t)cb * 128 * CDIM), hsb, ring, acc);
#pragma unroll
        for (int mt = 0; mt < 2; ++mt)
#pragma unroll
            for (int h = 0; h < 2; ++h) {
                int row = cb * 128 + rowL + mt * 16 + h * 8;   // channel c
                float bb = b2[row];
                size_t base = ((size_t)b * CDIM + row) * NTOK;
#pragma unroll
                for (int nt = 0; nt < 8; ++nt) {
                    int col = i0 + colL + nt * 8;
                    float2 xv = *(const float2*)(x + base + col);
                    *(float2*)(out + base + col)
                        = make_float2(acc[mt][nt][h*2]   + bb + xv.x,
                                      acc[mt][nt][h*2+1] + bb + xv.y);
                }
            }
        __syncthreads();   // ring reusable for next cb
    }
}

// ---------------- launch ----------------
extern "C" void kernel_launch(void* const* d_in, const int* in_sizes, int n_in,
                              void* d_out, int out_size)
{
    (void)in_sizes; (void)n_in; (void)out_size;
    const float* x  = (const float*)d_in[0];
    const float* WQ = (const float*)d_in[1];
    const float* bQ = (const float*)d_in[2];
    const float* WK = (const float*)d_in[3];
    const float* bK = (const float*)d_in[4];
    const float* WV = (const float*)d_in[5];
    const float* bV = (const float*)d_in[6];
    const float* PE = (const float*)d_in[7];
    const float* W1 = (const float*)d_in[8];
    const float* b1 = (const float*)d_in[9];
    const float* W2 = (const float*)d_in[10];
    const float* b2 = (const float*)d_in[11];
    float* out = (float*)d_out;

    cudaFuncSetAttribute(k_projqk_w, cudaFuncAttributeMaxDynamicSharedMemorySize, SMEM4);
    cudaFuncSetAttribute(k_qkt_w,    cudaFuncAttributeMaxDynamicSharedMemorySize, SMEM2);
    cudaFuncSetAttribute(k_projv_w,  cudaFuncAttributeMaxDynamicSharedMemorySize, SMEM4);
    cudaFuncSetAttribute(k_av_w,     cudaFuncAttributeMaxDynamicSharedMemorySize, SMEM4);
    cudaFuncSetAttribute(k_mlp_f,    cudaFuncAttributeMaxDynamicSharedMemorySize, MLP_SMEM);

    k_pre     <<<dim3(1340),        256>>>(x, PE, W1, W2, WV, WQ, WK);
    k_projqk_w<<<dim3(32, NB),      256, SMEM4>>>(bQ, bK);
    k_qkt_w   <<<dim3(32, 32, NB),  256, SMEM2>>>();
    k_projv_w <<<dim3(32, 2, NB),   256, SMEM4>>>(bV);
    k_av_w    <<<dim3(2, 32, NB),   256, SMEM4>>>();
    k_mlp_f   <<<dim3(32, NB),      256, MLP_SMEM>>>(b1, b2, x, out);
}

// round 17
// speedup vs baseline: 1.0479x; 1.0291x over previous
#include <cuda_runtime.h>
#include <cuda_bf16.h>
#include <math.h>
#include <cstdint>

#define NTOK 4096
#define CDIM 256
#define QKD  64
#define NB   4

typedef unsigned long long u64;

// ---------------- scratch (device globals) ----------------
__device__ __align__(256) __nv_bfloat16 g_xt  [(size_t)NB * NTOK * CDIM];  // [b][j][c] bf16
__device__ __align__(256) float         g_pet [(size_t)NTOK * QKD];        // PE^T [i][d] fp32
__device__ __align__(256) __nv_bfloat16 g_qb  [(size_t)NB * NTOK * QKD];   // [b][i][d] (pre-scaled)
__device__ __align__(256) __nv_bfloat16 g_kb  [(size_t)NB * NTOK * QKD];   // [b][j][d]
__device__ __align__(256) uint8_t       g_E8  [(size_t)NB * NTOK * NTOK];  // [b][i][j] e4m3 exp(S)
__device__ __align__(256) uint8_t       g_vb8 [(size_t)NB * CDIM * NTOK];  // [b][c][j] e4m3 (V+b)*w*4096
__device__ __align__(256) float         g_cs  [NB * NTOK];                 // column sums (atomic)
__device__ __align__(256) __nv_bfloat16 g_aob [(size_t)NB * NTOK * CDIM];  // [b][i][c]
__device__ __align__(256) __nv_bfloat16 g_W1b [CDIM * CDIM];
__device__ __align__(256) __nv_bfloat16 g_W2b [CDIM * CDIM];
__device__ __align__(256) __nv_bfloat16 g_WVb [CDIM * CDIM];
__device__ __align__(256) __nv_bfloat16 g_WQKb[2 * QKD * CDIM];

// ---------------- PTX helpers ----------------
__device__ __forceinline__ uint32_t smem_u32(const void* p) {
    uint32_t a;
    asm("{ .reg .u64 t; cvta.to.shared.u64 t, %1; cvt.u32.u64 %0, t; }" : "=r"(a) : "l"(p));
    return a;
}
#define CP_COMMIT()  asm volatile("cp.async.commit_group;" ::: "memory")
template <int N>
__device__ __forceinline__ void cp_wait() {
    asm volatile("cp.async.wait_group %0;" :: "n"(N) : "memory");
}
__device__ __forceinline__ void cp16(uint32_t d, const void* s) {
    asm volatile("cp.async.cg.shared.global [%0], [%1], 16;" :: "r"(d), "l"(s) : "memory");
}
__device__ __forceinline__ void ldsm4(uint32_t r[4], uint32_t a) {
    asm volatile("ldmatrix.sync.aligned.m8n8.x4.shared.b16 {%0,%1,%2,%3}, [%4];"
                 : "=r"(r[0]), "=r"(r[1]), "=r"(r[2]), "=r"(r[3]) : "r"(a));
}
__device__ __forceinline__ void mma_bf16(float c[4], const uint32_t a[4], const uint32_t b[2]) {
    asm volatile("mma.sync.aligned.m16n8k16.row.col.f32.bf16.bf16.f32 "
                 "{%0,%1,%2,%3}, {%4,%5,%6,%7}, {%8,%9}, {%0,%1,%2,%3};"
                 : "+f"(c[0]), "+f"(c[1]), "+f"(c[2]), "+f"(c[3])
                 : "r"(a[0]), "r"(a[1]), "r"(a[2]), "r"(a[3]), "r"(b[0]), "r"(b[1]));
}
__device__ __forceinline__ void mma_fp8(float c[4], const uint32_t a[4], const uint32_t b[2]) {
    asm volatile("mma.sync.aligned.m16n8k32.row.col.f32.e4m3.e4m3.f32 "
                 "{%0,%1,%2,%3}, {%4,%5,%6,%7}, {%8,%9}, {%0,%1,%2,%3};"
                 : "+f"(c[0]), "+f"(c[1]), "+f"(c[2]), "+f"(c[3])
                 : "r"(a[0]), "r"(a[1]), "r"(a[2]), "r"(a[3]), "r"(b[0]), "r"(b[1]));
}
__device__ __forceinline__ uint32_t bf2(float x, float y) {
    __nv_bfloat162 h = __floats2bfloat162_rn(x, y);
    return *(uint32_t*)&h;
}
__device__ __forceinline__ unsigned short fp8x2(float lo, float hi) {
    unsigned short r;
    asm("cvt.rn.satfinite.e4m3x2.f32 %0, %1, %2;" : "=h"(r) : "f"(hi), "f"(lo));
    return r;
}
__device__ __forceinline__ uint32_t ex2_bf16x2(uint32_t a) {
    uint32_t d; asm("ex2.approx.ftz.bf16x2 %0, %1;" : "=r"(d) : "r"(a)); return d;
}
__device__ __forceinline__ float ex2f(float x) {
    float y; asm("ex2.approx.f32 %0, %1;" : "=f"(y) : "f"(x)); return y;
}
__device__ __forceinline__ float lg2f_a(float x) {
    float y; asm("lg2.approx.f32 %0, %1;" : "=f"(y) : "f"(x)); return y;
}
__device__ __forceinline__ float tanh_a(float x) {
    float y; asm("tanh.approx.f32 %0, %1;" : "=f"(y) : "f"(x)); return y;
}
__device__ __forceinline__ float mishf(float v) {
    float t  = ex2f(v * 1.4426950408889634f);
    float sp = lg2f_a(1.0f + t) * 0.6931471805599453f;
    return v * tanh_a(sp);
}
#define QK_SCL 0.18033688011112042f   /* 0.125 * log2(e), folded into Q */
#define AV_SCL 0.000244140625f        /* 1/4096, undoes Vb rescale */

// ================= shared warp-MMA GEMM mainloop =================
// CTA: 256 thr (8 warps, 4 M x 2 N), tile 128(M) x 128(N).
// K-chunk = 64 bytes/row: 32 bf16 or 64 e4m3.
// Single barrier per chunk: refill targets stage (c+NST-1)%NST = (c-1)%NST,
// whose reads completed before this chunk's barrier (warps are <=1 barrier apart).
#define ROWB   80
#define SBOFF  (128 * ROWB)
#define STG    (2 * 128 * ROWB)
#define SMEM4  (4 * STG)
#define SMEM3  (3 * STG)

template <int NCH, int NST, bool FP8>
__device__ __forceinline__ void gemm_main(const char* __restrict__ gA, size_t lda,
                                          const char* __restrict__ gB, size_t ldb,
                                          char* smem, float acc[2][8][4])
{
    const int tid  = threadIdx.x;
    const int lane = tid & 31, wid = tid >> 5;
    const int wr = wid & 3, wc = wid >> 2;
    const uint32_t sb = smem_u32(smem);
    const int r0  = tid >> 2;
    const int seg = tid & 3;

    const uint32_t aOff = (uint32_t)((wr * 32 + (lane & 15)) * ROWB + (lane >> 4) * 16);
    const uint32_t bOff = (uint32_t)(SBOFF + (wc * 64 + (lane & 7)) * ROWB + ((lane >> 3) & 3) * 16);

#pragma unroll
    for (int s = 0; s < NST - 1; ++s) {
        if (s < NCH) {
            uint32_t base = sb + (s % NST) * STG;
#pragma unroll
            for (int h = 0; h < 2; ++h) {
                int row = r0 + h * 64;
                cp16(base + row * ROWB + seg * 16, gA + (size_t)row * lda + (size_t)s * 64 + seg * 16);
                cp16(base + SBOFF + row * ROWB + seg * 16, gB + (size_t)row * ldb + (size_t)s * 64 + seg * 16);
            }
        }
        CP_COMMIT();
    }
    for (int c = 0; c < NCH; ++c) {
        cp_wait<NST - 2>();
        __syncthreads();
        const uint32_t st = sb + (c % NST) * STG;
        uint32_t af[2][2][4], bf[8][4];
#pragma unroll
        for (int mt = 0; mt < 2; ++mt)
#pragma unroll
            for (int ks = 0; ks < 2; ++ks)
                ldsm4(af[mt][ks], st + aOff + mt * (16 * ROWB) + ks * 32);
#pragma unroll
        for (int nt = 0; nt < 8; ++nt)
            ldsm4(bf[nt], st + bOff + nt * (8 * ROWB));
        if (c + NST - 1 < NCH) {
            uint32_t base = sb + ((c + NST - 1) % NST) * STG;
#pragma unroll
            for (int h = 0; h < 2; ++h) {
                int row = r0 + h * 64;
                cp16(base + row * ROWB + seg * 16, gA + (size_t)row * lda + (size_t)(c + NST - 1) * 64 + seg * 16);
                cp16(base + SBOFF + row * ROWB + seg * 16, gB + (size_t)row * ldb + (size_t)(c + NST - 1) * 64 + seg * 16);
            }
        }
        CP_COMMIT();
#pragma unroll
        for (int ks = 0; ks < 2; ++ks)
#pragma unroll
            for (int mt = 0; mt < 2; ++mt)
#pragma unroll
                for (int nt = 0; nt < 8; ++nt) {
                    if (FP8) mma_fp8(acc[mt][nt], af[mt][ks], &bf[nt][ks * 2]);
                    else     mma_bf16(acc[mt][nt], af[mt][ks], &bf[nt][ks * 2]);
                }
    }
}

// ---- phase-2 mainloop for fused MLP: A streamed via A-only ring, B from persistent smem H ----
// K = 256 (o). A-ring stage = 64 B/row = 32 k per chunk -> 8 chunks. H offset per chunk = 64 B.
#define HROWB 528                       /* bytes per H row: 256 bf16 data (512B) + 16B pad */
#define ASTG  (128 * ROWB)              /* A-only stage = 10240 B */
__device__ __forceinline__ void gemm_w2(const char* __restrict__ gA,
                                        uint32_t hsb, char* ring, float acc[2][8][4])
{
    const int tid  = threadIdx.x;
    const int lane = tid & 31, wid = tid >> 5;
    const int wr = wid & 3, wc = wid >> 2;
    const uint32_t sb = smem_u32(ring);
    const int row = tid >> 1, sg = (tid & 1) * 2;

    const uint32_t aOff  = (uint32_t)((wr * 32 + (lane & 15)) * ROWB + (lane >> 4) * 16);
    const uint32_t bOffH = (uint32_t)((wc * 64 + (lane & 7)) * HROWB + ((lane >> 3) & 3) * 16);

#pragma unroll
    for (int s = 0; s < 3; ++s) {
        uint32_t base = sb + s * ASTG;
        cp16(base + row * ROWB + sg * 16,       gA + (size_t)row * 512 + (size_t)s * 64 + sg * 16);
        cp16(base + row * ROWB + (sg + 1) * 16, gA + (size_t)row * 512 + (size_t)s * 64 + (sg + 1) * 16);
        CP_COMMIT();
    }
    for (int c = 0; c < 8; ++c) {
        cp_wait<2>();
        __syncthreads();
        const uint32_t st = sb + (c & 3) * ASTG;
        uint32_t af[2][2][4], bf[8][4];
#pragma unroll
        for (int mt = 0; mt < 2; ++mt)
#pragma unroll
            for (int ks = 0; ks < 2; ++ks)
                ldsm4(af[mt][ks], st + aOff + mt * (16 * ROWB) + ks * 32);
#pragma unroll
        for (int nt = 0; nt < 8; ++nt)
            ldsm4(bf[nt], hsb + bOffH + nt * (8 * HROWB) + c * 64);
        if (c + 3 < 8) {
            uint32_t base = sb + ((c + 3) & 3) * ASTG;
            cp16(base + row * ROWB + sg * 16,       gA + (size_t)row * 512 + (size_t)(c + 3) * 64 + sg * 16);
            cp16(base + row * ROWB + (sg + 1) * 16, gA + (size_t)row * 512 + (size_t)(c + 3) * 64 + (sg + 1) * 16);
        }
        CP_COMMIT();
#pragma unroll
        for (int ks = 0; ks < 2; ++ks)
#pragma unroll
            for (int mt = 0; mt < 2; ++mt)
#pragma unroll
                for (int nt = 0; nt < 8; ++nt)
                    mma_bf16(acc[mt][nt], af[mt][ks], &bf[nt][ks * 2]);
    }
}

#define ACC_DECL  float acc[2][8][4]; \
    _Pragma("unroll") for (int _m = 0; _m < 2; ++_m) \
    _Pragma("unroll") for (int _n = 0; _n < 8; ++_n) \
    _Pragma("unroll") for (int _q = 0; _q < 4; ++_q) acc[_m][_n][_q] = 0.0f;

#define EPI_COORDS \
    const int lane = threadIdx.x & 31, wid = threadIdx.x >> 5; \
    const int wr = wid & 3, wc = wid >> 2; \
    const int rowL = wr * 32 + (lane >> 2); \
    const int colL = wc * 64 + (lane & 3) * 2; \
    (void)wr; (void)wc;

// ---------------- K0: merged pre-pass ----------------
__device__ __forceinline__ void conv4(const float* s, __nv_bfloat16* d, int i) {
    float4 v = *(const float4*)(s + i);
    *(uint32_t*)(d + i)     = bf2(v.x, v.y);
    *(uint32_t*)(d + i + 2) = bf2(v.z, v.w);
}
__global__ __launch_bounds__(256) void k_pre(
    const float* __restrict__ x, const float* __restrict__ PE,
    const float* __restrict__ W1, const float* __restrict__ W2, const float* __restrict__ WV,
    const float* __restrict__ WQ, const float* __restrict__ WK)
{
    __shared__ float ts[32][129];
    const int tid = threadIdx.x;
    const int gb = blockIdx.x;

    if (gb < 1024) {
        const int jt = (gb & 31) * 128, ct = ((gb >> 5) & 7) * 32, b = gb >> 8;
#pragma unroll
        for (int p = 0; p < 4; ++p) {
            int c = (tid >> 5) + p * 8;
            int j = (tid & 31) * 4;
            float4 v = *(const float4*)(x + ((size_t)b * CDIM + ct + c) * NTOK + jt + j);
            ts[c][j] = v.x; ts[c][j+1] = v.y; ts[c][j+2] = v.z; ts[c][j+3] = v.w;
        }
        __syncthreads();
#pragma unroll
        for (int p = 0; p < 8; ++p) {
            int idx = tid + p * 256;
            int j = idx >> 4, cp = idx & 15;
            *(uint32_t*)(g_xt + ((size_t)b * NTOK + jt + j) * CDIM + ct + cp * 2)
                = bf2(ts[cp * 2][j], ts[cp * 2 + 1][j]);
        }
    } else if (gb < 1280) {
        const int blk = gb - 1024;
        const int it = (blk & 127) * 32, dt = (blk >> 7) * 32;
        const int r = tid >> 5, c = tid & 31;
        float (*t2)[33] = (float(*)[33])ts;
#pragma unroll
        for (int p = 0; p < 4; ++p)
            t2[r + p * 8][c] = PE[(size_t)(dt + r + p * 8) * NTOK + it + c];
        __syncthreads();
#pragma unroll
        for (int p = 0; p < 4; ++p)
            g_pet[(size_t)(it + r + p * 8) * QKD + dt + c] = t2[c][r + p * 8];
    } else {
        const int blk = gb - 1280;
        if (blk < 16) {
            int base = blk * 4096;
#pragma unroll
            for (int p = 0; p < 4; ++p) conv4(W1, g_W1b, base + p * 1024 + tid * 4);
        } else if (blk < 32) {
            int base = (blk - 16) * 4096;
#pragma unroll
            for (int p = 0; p < 4; ++p) conv4(W2, g_W2b, base + p * 1024 + tid * 4);
        } else if (blk < 48) {
            int base = (blk - 32) * 4096;
#pragma unroll
            for (int p = 0; p < 4; ++p) conv4(WV, g_WVb, base + p * 1024 + tid * 4);
        } else if (blk < 56) {
            int base = (blk - 48) * 4096;
#pragma unroll
            for (int p = 0; p < 4; ++p) {
                int i = base + p * 1024 + tid * 4;
                const float* s = (i < QKD * CDIM) ? (WQ + i) : (WK + i - QKD * CDIM);
                float4 v = *(const float4*)s;
                *(uint32_t*)(g_WQKb + i)     = bf2(v.x, v.y);
                *(uint32_t*)(g_WQKb + i + 2) = bf2(v.z, v.w);
            }
        } else {
            int base = (blk - 56) * 4096;
#pragma unroll
            for (int p = 0; p < 4; ++p)
                *(float4*)(g_cs + base + p * 1024 + tid * 4) = make_float4(0.f, 0.f, 0.f, 0.f);
        }
    }
}

// ---------------- K1: QK projection; Q pre-scaled by QK_SCL ----------------
__global__ __launch_bounds__(256, 2) void k_projqk_w(
    const float* __restrict__ bQ, const float* __restrict__ bK)
{
    extern __shared__ char smem[];
    const int i0 = blockIdx.x * 128, b = blockIdx.y;
    ACC_DECL;
    gemm_main<8, 4, false>((const char*)(g_xt + ((size_t)b * NTOK + i0) * CDIM), 512,
                           (const char*)g_WQKb, 512, smem, acc);
    EPI_COORDS;
    const bool isQ = (wc == 0);
    const float scl = isQ ? QK_SCL : 1.0f;
    __nv_bfloat16* dst = (isQ ? g_qb : g_kb) + (size_t)b * NTOK * QKD;
#pragma unroll
    for (int nt = 0; nt < 8; ++nt) {
        int d = (lane & 3) * 2 + nt * 8;
        float b0 = isQ ? bQ[d]     : bK[d];
        float b1 = isQ ? bQ[d + 1] : bK[d + 1];
#pragma unroll
        for (int mt = 0; mt < 2; ++mt)
#pragma unroll
            for (int h = 0; h < 2; ++h) {
                int row = i0 + rowL + mt * 16 + h * 8;
                float2 pe = *(const float2*)(g_pet + (size_t)row * QKD + d);
                *(uint32_t*)(dst + (size_t)row * QKD + d)
                    = bf2((acc[mt][nt][h*2] + b0 + pe.x) * scl,
                          (acc[mt][nt][h*2+1] + b1 + pe.y) * scl);
            }
    }
}

// ---------------- K2: QK^T mma + exp -> e4m3 E (smem-staged coalesced) + colsum ----------------
// grid (32 j, 32 i, 4 b). Q pre-scaled, so E = 2^(acc). NST=3: both K-chunks prefetched.
#define EST8  144
__global__ __launch_bounds__(256, 2) void k_qkt_w()
{
    extern __shared__ char smem[];
    const int j0 = blockIdx.x * 128, i0 = blockIdx.y * 128, b = blockIdx.z;
    ACC_DECL;
    gemm_main<2, 3, false>((const char*)(g_qb + ((size_t)b * NTOK + i0) * QKD), 128,
                           (const char*)(g_kb + ((size_t)b * NTOK + j0) * QKD), 128,
                           smem, acc);
    EPI_COORDS;
    uint8_t* est = (uint8_t*)smem;     // 128 x 144B staging (18.4 KB)
    float cs[8][2];
#pragma unroll
    for (int nt = 0; nt < 8; ++nt) { cs[nt][0] = 0.f; cs[nt][1] = 0.f; }
    __syncthreads();                   // mainloop reads done before staging overwrite
#pragma unroll
    for (int mt = 0; mt < 2; ++mt)
#pragma unroll
        for (int nt = 0; nt < 8; ++nt) {
            int col = colL + nt * 8;
#pragma unroll
            for (int h = 0; h < 2; ++h) {
                int row = rowL + mt * 16 + h * 8;
                uint32_t ee = ex2_bf16x2(bf2(acc[mt][nt][h*2], acc[mt][nt][h*2+1]));
                float e0 = __int_as_float(ee << 16);
                float e1 = __int_as_float(ee & 0xFFFF0000u);
                *(unsigned short*)(est + row * EST8 + col) = fp8x2(e0, e1);
                cs[nt][0] += e0;
                cs[nt][1] += e1;
            }
        }
    __syncthreads();
    {
        const int tid = threadIdx.x;
        uint8_t* ep = g_E8 + ((size_t)b * NTOK + i0) * NTOK + j0;
#pragma unroll
        for (int p = 0; p < 4; ++p) {
            int idx = tid + p * 256;
            int row = idx >> 3, seg = idx & 7;
            uint4 v = *(const uint4*)(est + row * EST8 + seg * 16);
            *(uint4*)(ep + (size_t)row * NTOK + seg * 16) = v;
        }
    }
#pragma unroll
    for (int nt = 0; nt < 8; ++nt)
#pragma unroll
        for (int p = 0; p < 2; ++p) {
            float v = cs[nt][p];
            v += __shfl_xor_sync(0xFFFFFFFFu, v, 4);
            v += __shfl_xor_sync(0xFFFFFFFFu, v, 8);
            v += __shfl_xor_sync(0xFFFFFFFFu, v, 16);
            cs[nt][p] = v;
        }
    float* sred = (float*)smem;
    __syncthreads();
    if (threadIdx.x < 128) sred[threadIdx.x] = 0.0f;
    __syncthreads();
    if ((lane >> 2) == 0) {
#pragma unroll
        for (int nt = 0; nt < 8; ++nt) {
            int cc = wc * 64 + (lane & 3) * 2 + nt * 8;
            atomicAdd(&sred[cc],     cs[nt][0]);
            atomicAdd(&sred[cc + 1], cs[nt][1]);
        }
    }
    __syncthreads();
    if (threadIdx.x < 128)
        atomicAdd(&g_cs[(size_t)b * NTOK + j0 + threadIdx.x], sred[threadIdx.x]);
}

// ---------------- K3: V projection (epilogue: w = 4096/colsum inline, *w+bias -> e4m3) ----------------
__global__ __launch_bounds__(256, 2) void k_projv_w(const float* __restrict__ bV)
{
    extern __shared__ char smem[];
    const int j0 = blockIdx.x * 128, m0 = blockIdx.y * 128, b = blockIdx.z;
    ACC_DECL;
    gemm_main<8, 4, false>((const char*)(g_WVb + (size_t)m0 * CDIM), 512,
                           (const char*)(g_xt + ((size_t)b * NTOK + j0) * CDIM), 512,
                           smem, acc);
    EPI_COORDS;
    float wv[8][2];
#pragma unroll
    for (int nt = 0; nt < 8; ++nt) {
        int col = j0 + colL + nt * 8;
        float2 c2 = *(const float2*)(g_cs + (size_t)b * NTOK + col);
        wv[nt][0] = 4096.0f / c2.x;
        wv[nt][1] = 4096.0f / c2.y;
    }
#pragma unroll
    for (int mt = 0; mt < 2; ++mt)
#pragma unroll
        for (int h = 0; h < 2; ++h) {
            int row = m0 + rowL + mt * 16 + h * 8;
            float bb = bV[row];
#pragma unroll
            for (int nt = 0; nt < 8; ++nt) {
                int col = j0 + colL + nt * 8;
                *(unsigned short*)(g_vb8 + ((size_t)b * CDIM + row) * NTOK + col)
                    = fp8x2((acc[mt][nt][h*2] + bb) * wv[nt][0],
                            (acc[mt][nt][h*2+1] + bb) * wv[nt][1]);
            }
        }
}

// ---------------- K4: AO = E @ Vb (fp8 mma, K=4096) -> bf16 ao[i][c] ----------------
__global__ __launch_bounds__(256) void k_av_w()
{
    extern __shared__ char smem[];
    const int n0 = blockIdx.x * 128, i0 = blockIdx.y * 128, b = blockIdx.z;
    ACC_DECL;
    gemm_main<64, 4, true>((const char*)(g_E8  + ((size_t)b * NTOK + i0) * NTOK), 4096,
                           (const char*)(g_vb8 + ((size_t)b * CDIM + n0) * NTOK), 4096,
                           smem, acc);
    EPI_COORDS;
#pragma unroll
    for (int mt = 0; mt < 2; ++mt)
#pragma unroll
        for (int nt = 0; nt < 8; ++nt) {
            int col = n0 + colL + nt * 8;
#pragma unroll
            for (int h = 0; h < 2; ++h) {
                int row = i0 + rowL + mt * 16 + h * 8;
                *(uint32_t*)(g_aob + ((size_t)b * NTOK + row) * CDIM + col)
                    = bf2(acc[mt][nt][h*2] * AV_SCL, acc[mt][nt][h*2+1] * AV_SCL);
            }
        }
}

// ---------------- K5: fused MLP ----------------
#define MLP_SMEM (SMEM4 + 128 * HROWB)
__global__ __launch_bounds__(256) void k_mlp_f(
    const float* __restrict__ b1, const float* __restrict__ b2,
    const float* __restrict__ x, float* __restrict__ out)
{
    extern __shared__ char smem[];
    char* ring = smem;
    __nv_bfloat16* Hs = (__nv_bfloat16*)(smem + SMEM4);
    const uint32_t hsb = smem_u32(Hs);
    const int i0 = blockIdx.x * 128, b = blockIdx.y;
    EPI_COORDS;

#pragma unroll 1
    for (int ob = 0; ob < 2; ++ob) {
        ACC_DECL;
        gemm_main<8, 4, false>((const char*)(g_aob + ((size_t)b * NTOK + i0) * CDIM), 512,
                               (const char*)(g_W1b + (size_t)ob * 128 * CDIM), 512, ring, acc);
#pragma unroll
        for (int nt = 0; nt < 8; ++nt) {
            int col = ob * 128 + colL + nt * 8;
            float bb0 = b1[col], bb1 = b1[col + 1];
#pragma unroll
            for (int mt = 0; mt < 2; ++mt)
#pragma unroll
                for (int h = 0; h < 2; ++h) {
                    int row = rowL + mt * 16 + h * 8;
                    *(uint32_t*)((char*)Hs + row * HROWB + col * 2)
                        = bf2(mishf(acc[mt][nt][h*2] + bb0), mishf(acc[mt][nt][h*2+1] + bb1));
                }
        }
        __syncthreads();
    }

#pragma unroll 1
    for (int cb = 0; cb < 2; ++cb) {
        ACC_DECL;
        gemm_w2((const char*)(g_W2b + (size_t)cb * 128 * CDIM), hsb, ring, acc);
#pragma unroll
        for (int mt = 0; mt < 2; ++mt)
#pragma unroll
            for (int h = 0; h < 2; ++h) {
                int row = cb * 128 + rowL + mt * 16 + h * 8;
                float bb = b2[row];
                size_t base = ((size_t)b * CDIM + row) * NTOK;
#pragma unroll
                for (int nt = 0; nt < 8; ++nt) {
                    int col = i0 + colL + nt * 8;
                    float2 xv = *(const float2*)(x + base + col);
                    *(float2*)(out + base + col)
                        = make_float2(acc[mt][nt][h*2]   + bb + xv.x,
                                      acc[mt][nt][h*2+1] + bb + xv.y);
                }
            }
        __syncthreads();
    }
}

// ---------------- launch ----------------
extern "C" void kernel_launch(void* const* d_in, const int* in_sizes, int n_in,
                              void* d_out, int out_size)
{
    (void)in_sizes; (void)n_in; (void)out_size;
    const float* x  = (const float*)d_in[0];
    const float* WQ = (const float*)d_in[1];
    const float* bQ = (const float*)d_in[2];
    const float* WK = (const float*)d_in[3];
    const float* bK = (const float*)d_in[4];
    const float* WV = (const float*)d_in[5];
    const float* bV = (const float*)d_in[6];
    const float* PE = (const float*)d_in[7];
    const float* W1 = (const float*)d_in[8];
    const float* b1 = (const float*)d_in[9];
    const float* W2 = (const float*)d_in[10];
    const float* b2 = (const float*)d_in[11];
    float* out = (float*)d_out;

    cudaFuncSetAttribute(k_projqk_w, cudaFuncAttributeMaxDynamicSharedMemorySize, SMEM4);
    cudaFuncSetAttribute(k_qkt_w,    cudaFuncAttributeMaxDynamicSharedMemorySize, SMEM3);
    cudaFuncSetAttribute(k_projv_w,  cudaFuncAttributeMaxDynamicSharedMemorySize, SMEM4);
    cudaFuncSetAttribute(k_av_w,     cudaFuncAttributeMaxDynamicSharedMemorySize, SMEM4);
    cudaFuncSetAttribute(k_mlp_f,    cudaFuncAttributeMaxDynamicSharedMemorySize, MLP_SMEM);

    k_pre     <<<dim3(1340),        256>>>(x, PE, W1, W2, WV, WQ, WK);
    k_projqk_w<<<dim3(32, NB),      256, SMEM4>>>(bQ, bK);
    k_qkt_w   <<<dim3(32, 32, NB),  256, SMEM3>>>();
    k_projv_w <<<dim3(32, 2, NB),   256, SMEM4>>>(bV);
    k_av_w    <<<dim3(2, 32, NB),   256, SMEM4>>>();
    k_mlp_f   <<<dim3(32, NB),      256, MLP_SMEM>>>(b1, b2, x, out);
}